// round 6
// baseline (speedup 1.0000x reference)
#include <cuda_runtime.h>
#include <math.h>

#define BATCH 2
#define SEQ   2048
#define DIM   1024
#define NH    16
#define HD    64
#define MTOT  (BATCH*SEQ)   // 4096
#define QPAD  72            // padded row length for dim-major tiles (16B aligned, low conflict)
#define PPAD  68            // padded row length for P tile

// Scratch (allocation-free rule: device globals)
__device__ float g_q[MTOT*DIM];
__device__ float g_k[MTOT*DIM];
__device__ float g_v[MTOT*DIM];
__device__ float g_o[MTOT*DIM];

// ---------------------------------------------------------------------------
// C[M,N] = A[M,K] @ W[N,K]^T + bias[N]
// Block tile 64x64, BK=32, 256 threads, 4x4 micro-tile per thread.
// ---------------------------------------------------------------------------
__global__ __launch_bounds__(256) void gemm_bias_kernel(
    const float* __restrict__ A, const float* __restrict__ W,
    const float* __restrict__ bias, float* __restrict__ C,
    int M, int N, int K)
{
    constexpr int BK = 32;
    __shared__ float As[BK*QPAD];
    __shared__ float Ws[BK*QPAD];

    const int tid = threadIdx.x;
    const int tx  = tid & 15;
    const int ty  = tid >> 4;
    const int m0  = blockIdx.y * 64;
    const int n0  = blockIdx.x * 64;

    float acc[4][4] = {};

    for (int kt = 0; kt < K; kt += BK) {
        // 64 rows x 32 k = 512 float4 over 256 threads (2 iters)
        #pragma unroll
        for (int it = 0; it < 2; ++it) {
            int idx = tid + it * 256;
            int row = idx >> 3;              // 0..63
            int kq  = (idx & 7) << 2;        // 0,4,...,28
            float4 a = *reinterpret_cast<const float4*>(A + (size_t)(m0 + row) * K + kt + kq);
            As[(kq+0)*QPAD + row] = a.x;
            As[(kq+1)*QPAD + row] = a.y;
            As[(kq+2)*QPAD + row] = a.z;
            As[(kq+3)*QPAD + row] = a.w;
            float4 w = *reinterpret_cast<const float4*>(W + (size_t)(n0 + row) * K + kt + kq);
            Ws[(kq+0)*QPAD + row] = w.x;
            Ws[(kq+1)*QPAD + row] = w.y;
            Ws[(kq+2)*QPAD + row] = w.z;
            Ws[(kq+3)*QPAD + row] = w.w;
        }
        __syncthreads();

        #pragma unroll
        for (int kk = 0; kk < BK; ++kk) {
            float4 a4 = *reinterpret_cast<float4*>(As + kk*QPAD + ty*4);
            float4 w4 = *reinterpret_cast<float4*>(Ws + kk*QPAD + tx*4);
            float av[4] = {a4.x, a4.y, a4.z, a4.w};
            float wv[4] = {w4.x, w4.y, w4.z, w4.w};
            #pragma unroll
            for (int i = 0; i < 4; ++i)
                #pragma unroll
                for (int j = 0; j < 4; ++j)
                    acc[i][j] += av[i] * wv[j];
        }
        __syncthreads();
    }

    const float4 b4 = *reinterpret_cast<const float4*>(bias + n0 + tx*4);
    #pragma unroll
    for (int i = 0; i < 4; ++i) {
        float4 o;
        o.x = acc[i][0] + b4.x;
        o.y = acc[i][1] + b4.y;
        o.z = acc[i][2] + b4.z;
        o.w = acc[i][3] + b4.w;
        *reinterpret_cast<float4*>(C + (size_t)(m0 + ty*4 + i) * N + n0 + tx*4) = o;
    }
}

// ---------------------------------------------------------------------------
// Causal flash attention, one CTA per (query-block 64, head, batch).
// NOTE: attention tiles are 64x64 floats = 1024 float4 -> 4 load iterations,
// row = idx>>4, kq = (idx&15)<<2.  (R1 bug: used the GEMM's 64x32 pattern.)
// ---------------------------------------------------------------------------
__global__ __launch_bounds__(256) void attn_kernel(
    const float* __restrict__ Q, const float* __restrict__ Kg,
    const float* __restrict__ Vg, float* __restrict__ O)
{
    extern __shared__ float sm[];
    float* Qs = sm;                  // [64 dims][QPAD]  (dim-major, pre-scaled)
    float* Ks = sm + 64*QPAD;        // [64 dims][QPAD]  (dim-major)
    float* Vs = sm + 2*64*QPAD;      // [64 keys][QPAD]  (natural: key-major)
    float* Ps = sm + 3*64*QPAD;      // [64 rows][PPAD]

    const int tid = threadIdx.x;
    const int tx  = tid & 15;
    const int ty  = tid >> 4;
    const int qb  = blockIdx.x;
    const int h   = blockIdx.y;
    const int b   = blockIdx.z;
    const size_t base = ((size_t)b * SEQ) * DIM + (size_t)h * HD;
    const float scale = 0.125f;      // 1/sqrt(64)

    // Load Q tile (transposed, pre-scaled): 64 rows x 64 dims = 1024 float4
    #pragma unroll
    for (int it = 0; it < 4; ++it) {
        int idx = tid + it * 256;
        int row = idx >> 4;          // 0..63
        int kq  = (idx & 15) << 2;   // 0,4,...,60
        float4 qv = *reinterpret_cast<const float4*>(Q + base + (size_t)(qb*64 + row) * DIM + kq);
        Qs[(kq+0)*QPAD + row] = qv.x * scale;
        Qs[(kq+1)*QPAD + row] = qv.y * scale;
        Qs[(kq+2)*QPAD + row] = qv.z * scale;
        Qs[(kq+3)*QPAD + row] = qv.w * scale;
    }

    float m_i[4], l_i[4], acc[4][4];
    #pragma unroll
    for (int i = 0; i < 4; ++i) {
        m_i[i] = -1e30f;
        l_i[i] = 0.f;
        #pragma unroll
        for (int j = 0; j < 4; ++j) acc[i][j] = 0.f;
    }

    for (int kb = 0; kb <= qb; ++kb) {
        // Load K (transposed) and V (natural) tiles: 1024 float4 each
        #pragma unroll
        for (int it = 0; it < 4; ++it) {
            int idx = tid + it * 256;
            int row = idx >> 4;          // 0..63
            int kq  = (idx & 15) << 2;   // 0..60
            size_t g = base + (size_t)(kb*64 + row) * DIM + kq;
            float4 kv = *reinterpret_cast<const float4*>(Kg + g);
            Ks[(kq+0)*QPAD + row] = kv.x;
            Ks[(kq+1)*QPAD + row] = kv.y;
            Ks[(kq+2)*QPAD + row] = kv.z;
            Ks[(kq+3)*QPAD + row] = kv.w;
            float4 vv = *reinterpret_cast<const float4*>(Vg + g);
            *reinterpret_cast<float4*>(Vs + row*QPAD + kq) = vv;
        }
        __syncthreads();

        // S = (Q*scale) @ K^T  (64x64 per CTA, 4x4 per thread)
        float s[4][4] = {};
        #pragma unroll
        for (int kk = 0; kk < 64; ++kk) {
            float4 q4 = *reinterpret_cast<float4*>(Qs + kk*QPAD + ty*4);
            float4 k4 = *reinterpret_cast<float4*>(Ks + kk*QPAD + tx*4);
            float qv[4] = {q4.x, q4.y, q4.z, q4.w};
            float kv[4] = {k4.x, k4.y, k4.z, k4.w};
            #pragma unroll
            for (int i = 0; i < 4; ++i)
                #pragma unroll
                for (int j = 0; j < 4; ++j)
                    s[i][j] += qv[i] * kv[j];
        }

        // Causal mask (diagonal block only)
        if (kb == qb) {
            #pragma unroll
            for (int i = 0; i < 4; ++i)
                #pragma unroll
                for (int j = 0; j < 4; ++j)
                    if (tx*4 + j > ty*4 + i) s[i][j] = -1e30f;
        }

        // Online softmax: rows owned by 16 lanes (width-16 shfl reductions)
        #pragma unroll
        for (int i = 0; i < 4; ++i) {
            float mx = fmaxf(fmaxf(s[i][0], s[i][1]), fmaxf(s[i][2], s[i][3]));
            #pragma unroll
            for (int off = 8; off; off >>= 1)
                mx = fmaxf(mx, __shfl_xor_sync(0xffffffffu, mx, off, 16));
            float mn   = fmaxf(m_i[i], mx);
            float corr = __expf(m_i[i] - mn);
            m_i[i] = mn;
            float4 p;
            p.x = __expf(s[i][0] - mn);
            p.y = __expf(s[i][1] - mn);
            p.z = __expf(s[i][2] - mn);
            p.w = __expf(s[i][3] - mn);
            float rs = p.x + p.y + p.z + p.w;
            #pragma unroll
            for (int off = 8; off; off >>= 1)
                rs += __shfl_xor_sync(0xffffffffu, rs, off, 16);
            l_i[i] = l_i[i] * corr + rs;
            #pragma unroll
            for (int j = 0; j < 4; ++j) acc[i][j] *= corr;
            *reinterpret_cast<float4*>(Ps + (ty*4 + i)*PPAD + tx*4) = p;
        }
        __syncthreads();

        // O += P @ V
        #pragma unroll
        for (int kk = 0; kk < 64; ++kk) {
            float4 v4 = *reinterpret_cast<float4*>(Vs + kk*QPAD + tx*4);
            #pragma unroll
            for (int i = 0; i < 4; ++i) {
                float pv = Ps[(ty*4 + i)*PPAD + kk];
                acc[i][0] += pv * v4.x;
                acc[i][1] += pv * v4.y;
                acc[i][2] += pv * v4.z;
                acc[i][3] += pv * v4.w;
            }
        }
        __syncthreads();
    }

    // Normalize and write out in [B,S,H*HD] layout
    #pragma unroll
    for (int i = 0; i < 4; ++i) {
        float inv = 1.f / l_i[i];
        float4 o;
        o.x = acc[i][0] * inv;
        o.y = acc[i][1] * inv;
        o.z = acc[i][2] * inv;
        o.w = acc[i][3] * inv;
        *reinterpret_cast<float4*>(O + base + (size_t)(qb*64 + ty*4 + i) * DIM + tx*4) = o;
    }
}

// ---------------------------------------------------------------------------
extern "C" void kernel_launch(void* const* d_in, const int* in_sizes, int n_in,
                              void* d_out, int out_size)
{
    const float* x  = (const float*)d_in[0];
    const float* Wq = (const float*)d_in[1];
    const float* bq = (const float*)d_in[2];
    const float* Wk = (const float*)d_in[3];
    const float* bk = (const float*)d_in[4];
    const float* Wv = (const float*)d_in[5];
    const float* bv = (const float*)d_in[6];
    const float* Wo = (const float*)d_in[7];
    const float* bo = (const float*)d_in[8];

    float *q, *k, *v, *o;
    cudaGetSymbolAddress((void**)&q, g_q);
    cudaGetSymbolAddress((void**)&k, g_k);
    cudaGetSymbolAddress((void**)&v, g_v);
    cudaGetSymbolAddress((void**)&o, g_o);

    dim3 ggrid(DIM/64, MTOT/64);  // (16, 64)

    gemm_bias_kernel<<<ggrid, 256>>>(x, Wq, bq, q, MTOT, DIM, DIM);
    gemm_bias_kernel<<<ggrid, 256>>>(x, Wk, bk, k, MTOT, DIM, DIM);
    gemm_bias_kernel<<<ggrid, 256>>>(x, Wv, bv, v, MTOT, DIM, DIM);

    int smem = (3*64*QPAD + 64*PPAD) * (int)sizeof(float);  // 72704 B
    cudaFuncSetAttribute(attn_kernel, cudaFuncAttributeMaxDynamicSharedMemorySize, smem);
    attn_kernel<<<dim3(SEQ/64, NH, BATCH), 256, smem>>>(q, k, v, o);

    gemm_bias_kernel<<<ggrid, 256>>>(o, Wo, bo, (float*)d_out, MTOT, DIM, DIM);
}

// round 7
// speedup vs baseline: 1.3852x; 1.3852x over previous
#include <cuda_runtime.h>
#include <math.h>
#include <stdint.h>

#define BATCH 2
#define SEQ   2048
#define DIM   1024
#define NH    16
#define HD    64
#define MTOT  (BATCH*SEQ)   // 4096
#define QPAD  72
#define PPAD  68

// GEMM tiling
#define BM 128
#define BN 64
#define BKC 32
#define KPAD 36

// Scratch (allocation-free rule: device globals)
__device__ float g_q[MTOT*DIM];
__device__ float g_k[MTOT*DIM];
__device__ float g_v[MTOT*DIM];
__device__ float g_o[MTOT*DIM];

// ---------------------------------------------------------------------------
// tf32 helpers: 3xTF32 split for ~fp32-accurate tensor-core GEMM
// ---------------------------------------------------------------------------
__device__ __forceinline__ uint32_t f2tf32(float x) {
    uint32_t r;
    asm("cvt.rna.tf32.f32 %0, %1;" : "=r"(r) : "f"(x));
    return r;
}
__device__ __forceinline__ void split_tf32(float x, uint32_t& hi, uint32_t& lo) {
    hi = f2tf32(x);
    lo = f2tf32(x - __uint_as_float(hi));
}

#define MMA_TF32(c, a, b)                                                      \
    asm volatile(                                                              \
        "mma.sync.aligned.m16n8k8.row.col.f32.tf32.tf32.f32 "                  \
        "{%0,%1,%2,%3}, {%4,%5,%6,%7}, {%8,%9}, {%0,%1,%2,%3};"                \
        : "+f"((c)[0]), "+f"((c)[1]), "+f"((c)[2]), "+f"((c)[3])               \
        : "r"((a)[0]), "r"((a)[1]), "r"((a)[2]), "r"((a)[3]),                  \
          "r"((b)[0]), "r"((b)[1]))

// ---------------------------------------------------------------------------
// C[M,N] = A[M,K] @ W[N,K]^T + bias[N]   via 3xTF32 mma.sync
// CTA tile 128x64, BK=32, 256 threads = 8 warps (4m x 2n), warp tile 32x32.
// ---------------------------------------------------------------------------
__global__ __launch_bounds__(256) void gemm_tf32_kernel(
    const float* __restrict__ A, const float* __restrict__ W,
    const float* __restrict__ bias, float* __restrict__ C,
    int M, int N, int K)
{
    __shared__ float As[BM*KPAD];
    __shared__ float Bs[BN*KPAD];

    const int tid  = threadIdx.x;
    const int wid  = tid >> 5;
    const int lane = tid & 31;
    const int quad = lane >> 2;   // 0..7
    const int tq   = lane & 3;    // 0..3
    const int wm   = (wid & 3) * 32;   // warp m offset within CTA tile
    const int wn   = (wid >> 2) * 32;  // warp n offset
    const int m0   = blockIdx.y * BM;
    const int n0   = blockIdx.x * BN;

    float c[2][4][4];   // [m16 tile][n8 tile][frag]
    #pragma unroll
    for (int mt = 0; mt < 2; ++mt)
        #pragma unroll
        for (int nt = 0; nt < 4; ++nt)
            #pragma unroll
            for (int r = 0; r < 4; ++r) c[mt][nt][r] = 0.f;

    for (int kt = 0; kt < K; kt += BKC) {
        // Load A tile: 128 rows x 32 k = 1024 float4 over 256 threads (4 iters)
        #pragma unroll
        for (int it = 0; it < 4; ++it) {
            int idx = tid + it * 256;
            int row = idx >> 3;            // 0..127
            int kq  = (idx & 7) << 2;      // 0..28
            float4 a = *reinterpret_cast<const float4*>(A + (size_t)(m0 + row) * K + kt + kq);
            *reinterpret_cast<float4*>(As + row * KPAD + kq) = a;
        }
        // Load B tile (W rows): 64 x 32 = 512 float4 (2 iters)
        #pragma unroll
        for (int it = 0; it < 2; ++it) {
            int idx = tid + it * 256;
            int row = idx >> 3;            // 0..63
            int kq  = (idx & 7) << 2;
            float4 w = *reinterpret_cast<const float4*>(W + (size_t)(n0 + row) * K + kt + kq);
            *reinterpret_cast<float4*>(Bs + row * KPAD + kq) = w;
        }
        __syncthreads();

        #pragma unroll
        for (int kk = 0; kk < BKC; kk += 8) {
            // A fragments (m16k8, row-major): rows quad/quad+8, cols tq/tq+4
            uint32_t ahi[2][4], alo[2][4];
            #pragma unroll
            for (int mt = 0; mt < 2; ++mt) {
                int rbase = (wm + mt * 16 + quad) * KPAD + kk + tq;
                float a0 = As[rbase];
                float a1 = As[rbase + 8 * KPAD];
                float a2 = As[rbase + 4];
                float a3 = As[rbase + 8 * KPAD + 4];
                split_tf32(a0, ahi[mt][0], alo[mt][0]);
                split_tf32(a1, ahi[mt][1], alo[mt][1]);
                split_tf32(a2, ahi[mt][2], alo[mt][2]);
                split_tf32(a3, ahi[mt][3], alo[mt][3]);
            }
            // B fragments (k8n8, col-major == W[n][k] row-major): n=quad, k=tq/tq+4
            uint32_t bhi[4][2], blo[4][2];
            #pragma unroll
            for (int nt = 0; nt < 4; ++nt) {
                int rbase = (wn + nt * 8 + quad) * KPAD + kk + tq;
                float b0 = Bs[rbase];
                float b1 = Bs[rbase + 4];
                split_tf32(b0, bhi[nt][0], blo[nt][0]);
                split_tf32(b1, bhi[nt][1], blo[nt][1]);
            }
            #pragma unroll
            for (int mt = 0; mt < 2; ++mt)
                #pragma unroll
                for (int nt = 0; nt < 4; ++nt) {
                    MMA_TF32(c[mt][nt], ahi[mt], bhi[nt]);
                    MMA_TF32(c[mt][nt], ahi[mt], blo[nt]);
                    MMA_TF32(c[mt][nt], alo[mt], bhi[nt]);
                }
        }
        __syncthreads();
    }

    // Epilogue: C frag (m16n8): c0 (g, 2t), c1 (g, 2t+1), c2 (g+8, 2t), c3 (g+8, 2t+1)
    #pragma unroll
    for (int mt = 0; mt < 2; ++mt) {
        #pragma unroll
        for (int nt = 0; nt < 4; ++nt) {
            int row = m0 + wm + mt * 16 + quad;
            int col = n0 + wn + nt * 8 + tq * 2;
            float bx = bias[col], by = bias[col + 1];
            float2 o0 = make_float2(c[mt][nt][0] + bx, c[mt][nt][1] + by);
            float2 o1 = make_float2(c[mt][nt][2] + bx, c[mt][nt][3] + by);
            *reinterpret_cast<float2*>(C + (size_t)row * N + col)       = o0;
            *reinterpret_cast<float2*>(C + (size_t)(row + 8) * N + col) = o1;
        }
    }
}

// ---------------------------------------------------------------------------
// Causal flash attention (unchanged from R6-passing version).
// ---------------------------------------------------------------------------
__global__ __launch_bounds__(256) void attn_kernel(
    const float* __restrict__ Q, const float* __restrict__ Kg,
    const float* __restrict__ Vg, float* __restrict__ O)
{
    extern __shared__ float sm[];
    float* Qs = sm;                  // [64 dims][QPAD]
    float* Ks = sm + 64*QPAD;        // [64 dims][QPAD]
    float* Vs = sm + 2*64*QPAD;      // [64 keys][QPAD]
    float* Ps = sm + 3*64*QPAD;      // [64 rows][PPAD]

    const int tid = threadIdx.x;
    const int tx  = tid & 15;
    const int ty  = tid >> 4;
    const int qb  = blockIdx.x;
    const int h   = blockIdx.y;
    const int b   = blockIdx.z;
    const size_t base = ((size_t)b * SEQ) * DIM + (size_t)h * HD;
    const float scale = 0.125f;

    #pragma unroll
    for (int it = 0; it < 4; ++it) {
        int idx = tid + it * 256;
        int row = idx >> 4;
        int kq  = (idx & 15) << 2;
        float4 qv = *reinterpret_cast<const float4*>(Q + base + (size_t)(qb*64 + row) * DIM + kq);
        Qs[(kq+0)*QPAD + row] = qv.x * scale;
        Qs[(kq+1)*QPAD + row] = qv.y * scale;
        Qs[(kq+2)*QPAD + row] = qv.z * scale;
        Qs[(kq+3)*QPAD + row] = qv.w * scale;
    }

    float m_i[4], l_i[4], acc[4][4];
    #pragma unroll
    for (int i = 0; i < 4; ++i) {
        m_i[i] = -1e30f;
        l_i[i] = 0.f;
        #pragma unroll
        for (int j = 0; j < 4; ++j) acc[i][j] = 0.f;
    }

    for (int kb = 0; kb <= qb; ++kb) {
        #pragma unroll
        for (int it = 0; it < 4; ++it) {
            int idx = tid + it * 256;
            int row = idx >> 4;
            int kq  = (idx & 15) << 2;
            size_t g = base + (size_t)(kb*64 + row) * DIM + kq;
            float4 kv = *reinterpret_cast<const float4*>(Kg + g);
            Ks[(kq+0)*QPAD + row] = kv.x;
            Ks[(kq+1)*QPAD + row] = kv.y;
            Ks[(kq+2)*QPAD + row] = kv.z;
            Ks[(kq+3)*QPAD + row] = kv.w;
            float4 vv = *reinterpret_cast<const float4*>(Vg + g);
            *reinterpret_cast<float4*>(Vs + row*QPAD + kq) = vv;
        }
        __syncthreads();

        float s[4][4] = {};
        #pragma unroll
        for (int kk = 0; kk < 64; ++kk) {
            float4 q4 = *reinterpret_cast<float4*>(Qs + kk*QPAD + ty*4);
            float4 k4 = *reinterpret_cast<float4*>(Ks + kk*QPAD + tx*4);
            float qv[4] = {q4.x, q4.y, q4.z, q4.w};
            float kv[4] = {k4.x, k4.y, k4.z, k4.w};
            #pragma unroll
            for (int i = 0; i < 4; ++i)
                #pragma unroll
                for (int j = 0; j < 4; ++j)
                    s[i][j] += qv[i] * kv[j];
        }

        if (kb == qb) {
            #pragma unroll
            for (int i = 0; i < 4; ++i)
                #pragma unroll
                for (int j = 0; j < 4; ++j)
                    if (tx*4 + j > ty*4 + i) s[i][j] = -1e30f;
        }

        #pragma unroll
        for (int i = 0; i < 4; ++i) {
            float mx = fmaxf(fmaxf(s[i][0], s[i][1]), fmaxf(s[i][2], s[i][3]));
            #pragma unroll
            for (int off = 8; off; off >>= 1)
                mx = fmaxf(mx, __shfl_xor_sync(0xffffffffu, mx, off, 16));
            float mn   = fmaxf(m_i[i], mx);
            float corr = __expf(m_i[i] - mn);
            m_i[i] = mn;
            float4 p;
            p.x = __expf(s[i][0] - mn);
            p.y = __expf(s[i][1] - mn);
            p.z = __expf(s[i][2] - mn);
            p.w = __expf(s[i][3] - mn);
            float rs = p.x + p.y + p.z + p.w;
            #pragma unroll
            for (int off = 8; off; off >>= 1)
                rs += __shfl_xor_sync(0xffffffffu, rs, off, 16);
            l_i[i] = l_i[i] * corr + rs;
            #pragma unroll
            for (int j = 0; j < 4; ++j) acc[i][j] *= corr;
            *reinterpret_cast<float4*>(Ps + (ty*4 + i)*PPAD + tx*4) = p;
        }
        __syncthreads();

        #pragma unroll
        for (int kk = 0; kk < 64; ++kk) {
            float4 v4 = *reinterpret_cast<float4*>(Vs + kk*QPAD + tx*4);
            #pragma unroll
            for (int i = 0; i < 4; ++i) {
                float pv = Ps[(ty*4 + i)*PPAD + kk];
                acc[i][0] += pv * v4.x;
                acc[i][1] += pv * v4.y;
                acc[i][2] += pv * v4.z;
                acc[i][3] += pv * v4.w;
            }
        }
        __syncthreads();
    }

    #pragma unroll
    for (int i = 0; i < 4; ++i) {
        float inv = 1.f / l_i[i];
        float4 o;
        o.x = acc[i][0] * inv;
        o.y = acc[i][1] * inv;
        o.z = acc[i][2] * inv;
        o.w = acc[i][3] * inv;
        *reinterpret_cast<float4*>(O + base + (size_t)(qb*64 + ty*4 + i) * DIM + tx*4) = o;
    }
}

// ---------------------------------------------------------------------------
extern "C" void kernel_launch(void* const* d_in, const int* in_sizes, int n_in,
                              void* d_out, int out_size)
{
    const float* x  = (const float*)d_in[0];
    const float* Wq = (const float*)d_in[1];
    const float* bq = (const float*)d_in[2];
    const float* Wk = (const float*)d_in[3];
    const float* bk = (const float*)d_in[4];
    const float* Wv = (const float*)d_in[5];
    const float* bv = (const float*)d_in[6];
    const float* Wo = (const float*)d_in[7];
    const float* bo = (const float*)d_in[8];

    float *q, *k, *v, *o;
    cudaGetSymbolAddress((void**)&q, g_q);
    cudaGetSymbolAddress((void**)&k, g_k);
    cudaGetSymbolAddress((void**)&v, g_v);
    cudaGetSymbolAddress((void**)&o, g_o);

    dim3 ggrid(DIM/BN, MTOT/BM);  // (16, 32)

    gemm_tf32_kernel<<<ggrid, 256>>>(x, Wq, bq, q, MTOT, DIM, DIM);
    gemm_tf32_kernel<<<ggrid, 256>>>(x, Wk, bk, k, MTOT, DIM, DIM);
    gemm_tf32_kernel<<<ggrid, 256>>>(x, Wv, bv, v, MTOT, DIM, DIM);

    int smem = (3*64*QPAD + 64*PPAD) * (int)sizeof(float);  // 72704 B
    cudaFuncSetAttribute(attn_kernel, cudaFuncAttributeMaxDynamicSharedMemorySize, smem);
    attn_kernel<<<dim3(SEQ/64, NH, BATCH), 256, smem>>>(q, k, v, o);

    gemm_tf32_kernel<<<ggrid, 256>>>(o, Wo, bo, (float*)d_out, MTOT, DIM, DIM);
}

// round 8
// speedup vs baseline: 1.6245x; 1.1728x over previous
#include <cuda_runtime.h>
#include <math.h>
#include <stdint.h>

#define BATCH 2
#define SEQ   2048
#define DIM   1024
#define NH    16
#define HD    64
#define MTOT  (BATCH*SEQ)   // 4096

// GEMM tiling
#define BM 128
#define BN 64
#define BKC 32
#define KPAD 36

// Attention smem pads (chosen for conflict-free mma fragment access patterns)
#define KP 68   // K tile + P tile pad:  (quad*68 + tq) % 32 distinct over warp
#define VP 72   // V tile pad:           (tq*72 + quad) % 32 distinct over warp

// Scratch (allocation-free rule: device globals)
__device__ float g_q[MTOT*DIM];
__device__ float g_k[MTOT*DIM];
__device__ float g_v[MTOT*DIM];
__device__ float g_o[MTOT*DIM];

// ---------------------------------------------------------------------------
// tf32 helpers: 3xTF32 split for ~fp32-accurate tensor-core math
// ---------------------------------------------------------------------------
__device__ __forceinline__ uint32_t f2tf32(float x) {
    uint32_t r;
    asm("cvt.rna.tf32.f32 %0, %1;" : "=r"(r) : "f"(x));
    return r;
}
__device__ __forceinline__ void split_tf32(float x, uint32_t& hi, uint32_t& lo) {
    hi = f2tf32(x);
    lo = f2tf32(x - __uint_as_float(hi));
}

#define MMA_TF32(c, a, b)                                                      \
    asm volatile(                                                              \
        "mma.sync.aligned.m16n8k8.row.col.f32.tf32.tf32.f32 "                  \
        "{%0,%1,%2,%3}, {%4,%5,%6,%7}, {%8,%9}, {%0,%1,%2,%3};"                \
        : "+f"((c)[0]), "+f"((c)[1]), "+f"((c)[2]), "+f"((c)[3])               \
        : "r"((a)[0]), "r"((a)[1]), "r"((a)[2]), "r"((a)[3]),                  \
          "r"((b)[0]), "r"((b)[1]))

// ---------------------------------------------------------------------------
// C[M,N] = A[M,K] @ W[N,K]^T + bias[N]   via 3xTF32 mma.sync  (unchanged R7)
// ---------------------------------------------------------------------------
__global__ __launch_bounds__(256) void gemm_tf32_kernel(
    const float* __restrict__ A, const float* __restrict__ W,
    const float* __restrict__ bias, float* __restrict__ C,
    int M, int N, int K)
{
    __shared__ float As[BM*KPAD];
    __shared__ float Bs[BN*KPAD];

    const int tid  = threadIdx.x;
    const int wid  = tid >> 5;
    const int lane = tid & 31;
    const int quad = lane >> 2;
    const int tq   = lane & 3;
    const int wm   = (wid & 3) * 32;
    const int wn   = (wid >> 2) * 32;
    const int m0   = blockIdx.y * BM;
    const int n0   = blockIdx.x * BN;

    float c[2][4][4];
    #pragma unroll
    for (int mt = 0; mt < 2; ++mt)
        #pragma unroll
        for (int nt = 0; nt < 4; ++nt)
            #pragma unroll
            for (int r = 0; r < 4; ++r) c[mt][nt][r] = 0.f;

    for (int kt = 0; kt < K; kt += BKC) {
        #pragma unroll
        for (int it = 0; it < 4; ++it) {
            int idx = tid + it * 256;
            int row = idx >> 3;
            int kq  = (idx & 7) << 2;
            float4 a = *reinterpret_cast<const float4*>(A + (size_t)(m0 + row) * K + kt + kq);
            *reinterpret_cast<float4*>(As + row * KPAD + kq) = a;
        }
        #pragma unroll
        for (int it = 0; it < 2; ++it) {
            int idx = tid + it * 256;
            int row = idx >> 3;
            int kq  = (idx & 7) << 2;
            float4 w = *reinterpret_cast<const float4*>(W + (size_t)(n0 + row) * K + kt + kq);
            *reinterpret_cast<float4*>(Bs + row * KPAD + kq) = w;
        }
        __syncthreads();

        #pragma unroll
        for (int kk = 0; kk < BKC; kk += 8) {
            uint32_t ahi[2][4], alo[2][4];
            #pragma unroll
            for (int mt = 0; mt < 2; ++mt) {
                int rbase = (wm + mt * 16 + quad) * KPAD + kk + tq;
                split_tf32(As[rbase],              ahi[mt][0], alo[mt][0]);
                split_tf32(As[rbase + 8 * KPAD],   ahi[mt][1], alo[mt][1]);
                split_tf32(As[rbase + 4],          ahi[mt][2], alo[mt][2]);
                split_tf32(As[rbase + 8*KPAD + 4], ahi[mt][3], alo[mt][3]);
            }
            uint32_t bhi[4][2], blo[4][2];
            #pragma unroll
            for (int nt = 0; nt < 4; ++nt) {
                int rbase = (wn + nt * 8 + quad) * KPAD + kk + tq;
                split_tf32(Bs[rbase],     bhi[nt][0], blo[nt][0]);
                split_tf32(Bs[rbase + 4], bhi[nt][1], blo[nt][1]);
            }
            #pragma unroll
            for (int mt = 0; mt < 2; ++mt)
                #pragma unroll
                for (int nt = 0; nt < 4; ++nt) {
                    MMA_TF32(c[mt][nt], ahi[mt], bhi[nt]);
                    MMA_TF32(c[mt][nt], ahi[mt], blo[nt]);
                    MMA_TF32(c[mt][nt], alo[mt], bhi[nt]);
                }
        }
        __syncthreads();
    }

    #pragma unroll
    for (int mt = 0; mt < 2; ++mt) {
        #pragma unroll
        for (int nt = 0; nt < 4; ++nt) {
            int row = m0 + wm + mt * 16 + quad;
            int col = n0 + wn + nt * 8 + tq * 2;
            float bx = bias[col], by = bias[col + 1];
            float2 o0 = make_float2(c[mt][nt][0] + bx, c[mt][nt][1] + by);
            float2 o1 = make_float2(c[mt][nt][2] + bx, c[mt][nt][3] + by);
            *reinterpret_cast<float2*>(C + (size_t)row * N + col)       = o0;
            *reinterpret_cast<float2*>(C + (size_t)(row + 8) * N + col) = o1;
        }
    }
}

// ---------------------------------------------------------------------------
// Causal flash attention via 3xTF32 mma.sync.
// 1 CTA = 128 threads (4 warps) per (64-row q block, head, batch).
// Warp w owns q rows [16w, 16w+16): 8 n-tiles of m16n8k8 for both S and PV.
// Q frags live in registers (built once). K/V/P staged in smem with pads
// making all fragment loads bank-conflict-free.
// ---------------------------------------------------------------------------
__global__ __launch_bounds__(128) void attn_mma_kernel(
    const float* __restrict__ Q, const float* __restrict__ Kg,
    const float* __restrict__ Vg, float* __restrict__ O)
{
    extern __shared__ float sm[];
    float* Ks = sm;                       // [64][KP]   (key-major)
    float* Vs = sm + 64*KP;               // [64][VP]   (key-major)
    float* Ps = sm + 64*KP + 64*VP;       // [64][KP]

    const int tid  = threadIdx.x;
    const int wid  = tid >> 5;
    const int lane = tid & 31;
    const int quad = lane >> 2;           // 0..7
    const int tq   = lane & 3;            // 0..3
    const int wm   = wid * 16;            // warp's q-row base within tile

    const int qb = (SEQ/64 - 1) - blockIdx.x;   // big-work CTAs first
    const int h  = blockIdx.y;
    const int b  = blockIdx.z;
    const size_t base = ((size_t)b * SEQ) * DIM + (size_t)h * HD;
    const float scale = 0.125f;

    // ---- Stage Q tile (scaled) into Ks buffer, build A-frags in regs ----
    #pragma unroll
    for (int it = 0; it < 8; ++it) {
        int idx = tid + it * 128;          // 0..1023
        int row = idx >> 4;                // 0..63
        int kq  = (idx & 15) << 2;         // 0..60
        float4 qv = *reinterpret_cast<const float4*>(Q + base + (size_t)(qb*64 + row) * DIM + kq);
        qv.x *= scale; qv.y *= scale; qv.z *= scale; qv.w *= scale;
        *reinterpret_cast<float4*>(Ks + row * KP + kq) = qv;
    }
    __syncthreads();

    uint32_t qhi[8][4], qlo[8][4];
    #pragma unroll
    for (int kt = 0; kt < 8; ++kt) {
        int rb = (wm + quad) * KP + kt * 8 + tq;
        split_tf32(Ks[rb],            qhi[kt][0], qlo[kt][0]);
        split_tf32(Ks[rb + 8*KP],     qhi[kt][1], qlo[kt][1]);
        split_tf32(Ks[rb + 4],        qhi[kt][2], qlo[kt][2]);
        split_tf32(Ks[rb + 8*KP + 4], qhi[kt][3], qlo[kt][3]);
    }
    __syncthreads();

    float o[8][4];
    #pragma unroll
    for (int nt = 0; nt < 8; ++nt)
        #pragma unroll
        for (int r = 0; r < 4; ++r) o[nt][r] = 0.f;
    float m0v = -1e30f, m1v = -1e30f, l0 = 0.f, l1 = 0.f;

    for (int kb = 0; kb <= qb; ++kb) {
        // ---- Load K and V tiles ----
        #pragma unroll
        for (int it = 0; it < 8; ++it) {
            int idx = tid + it * 128;
            int row = idx >> 4;
            int kq  = (idx & 15) << 2;
            size_t g = base + (size_t)(kb*64 + row) * DIM + kq;
            float4 kv = *reinterpret_cast<const float4*>(Kg + g);
            *reinterpret_cast<float4*>(Ks + row * KP + kq) = kv;
            float4 vv = *reinterpret_cast<const float4*>(Vg + g);
            *reinterpret_cast<float4*>(Vs + row * VP + kq) = vv;
        }
        __syncthreads();

        // ---- S = Qs @ K^T  (m16 x n64, 3xTF32) ----
        float s[8][4];
        #pragma unroll
        for (int nt = 0; nt < 8; ++nt)
            #pragma unroll
            for (int r = 0; r < 4; ++r) s[nt][r] = 0.f;

        #pragma unroll
        for (int nt = 0; nt < 8; ++nt) {
            #pragma unroll
            for (int kt = 0; kt < 8; ++kt) {
                int rb = (nt * 8 + quad) * KP + kt * 8 + tq;
                uint32_t bh[2], bl[2];
                split_tf32(Ks[rb],     bh[0], bl[0]);
                split_tf32(Ks[rb + 4], bh[1], bl[1]);
                MMA_TF32(s[nt], qhi[kt], bh);
                MMA_TF32(s[nt], qhi[kt], bl);
                MMA_TF32(s[nt], qlo[kt], bh);
            }
        }

        // ---- Causal mask on diagonal block ----
        if (kb == qb) {
            int r0 = wm + quad, r1 = r0 + 8;
            #pragma unroll
            for (int nt = 0; nt < 8; ++nt) {
                int c0 = nt * 8 + 2 * tq, c1 = c0 + 1;
                if (c0 > r0) s[nt][0] = -1e30f;
                if (c1 > r0) s[nt][1] = -1e30f;
                if (c0 > r1) s[nt][2] = -1e30f;
                if (c1 > r1) s[nt][3] = -1e30f;
            }
        }

        // ---- Online softmax (rows quad and quad+8; reduce over tq group) ----
        float mx0 = -1e30f, mx1 = -1e30f;
        #pragma unroll
        for (int nt = 0; nt < 8; ++nt) {
            mx0 = fmaxf(mx0, fmaxf(s[nt][0], s[nt][1]));
            mx1 = fmaxf(mx1, fmaxf(s[nt][2], s[nt][3]));
        }
        mx0 = fmaxf(mx0, __shfl_xor_sync(0xffffffffu, mx0, 1));
        mx0 = fmaxf(mx0, __shfl_xor_sync(0xffffffffu, mx0, 2));
        mx1 = fmaxf(mx1, __shfl_xor_sync(0xffffffffu, mx1, 1));
        mx1 = fmaxf(mx1, __shfl_xor_sync(0xffffffffu, mx1, 2));

        float mn0 = fmaxf(m0v, mx0), mn1 = fmaxf(m1v, mx1);
        float c0 = __expf(m0v - mn0), c1 = __expf(m1v - mn1);
        m0v = mn0; m1v = mn1;

        float rs0 = 0.f, rs1 = 0.f;
        #pragma unroll
        for (int nt = 0; nt < 8; ++nt) {
            s[nt][0] = __expf(s[nt][0] - mn0);
            s[nt][1] = __expf(s[nt][1] - mn0);
            s[nt][2] = __expf(s[nt][2] - mn1);
            s[nt][3] = __expf(s[nt][3] - mn1);
            rs0 += s[nt][0] + s[nt][1];
            rs1 += s[nt][2] + s[nt][3];
            // stash P to smem (warp-private rows)
            *reinterpret_cast<float2*>(Ps + (wm + quad)     * KP + nt*8 + 2*tq) = make_float2(s[nt][0], s[nt][1]);
            *reinterpret_cast<float2*>(Ps + (wm + quad + 8) * KP + nt*8 + 2*tq) = make_float2(s[nt][2], s[nt][3]);
        }
        rs0 += __shfl_xor_sync(0xffffffffu, rs0, 1);
        rs0 += __shfl_xor_sync(0xffffffffu, rs0, 2);
        rs1 += __shfl_xor_sync(0xffffffffu, rs1, 1);
        rs1 += __shfl_xor_sync(0xffffffffu, rs1, 2);
        l0 = l0 * c0 + rs0;
        l1 = l1 * c1 + rs1;

        #pragma unroll
        for (int nt = 0; nt < 8; ++nt) {
            o[nt][0] *= c0; o[nt][1] *= c0;
            o[nt][2] *= c1; o[nt][3] *= c1;
        }
        __syncwarp();   // P rows read only by the warp that wrote them

        // ---- O += P @ V  (3xTF32) ----
        #pragma unroll
        for (int kt = 0; kt < 8; ++kt) {
            int pb = (wm + quad) * KP + kt * 8 + tq;
            uint32_t phi[4], plo[4];
            split_tf32(Ps[pb],            phi[0], plo[0]);
            split_tf32(Ps[pb + 8*KP],     phi[1], plo[1]);
            split_tf32(Ps[pb + 4],        phi[2], plo[2]);
            split_tf32(Ps[pb + 8*KP + 4], phi[3], plo[3]);
            #pragma unroll
            for (int nt = 0; nt < 8; ++nt) {
                int vb = (kt * 8 + tq) * VP + nt * 8 + quad;
                uint32_t vh[2], vl[2];
                split_tf32(Vs[vb],          vh[0], vl[0]);
                split_tf32(Vs[vb + 4*VP],   vh[1], vl[1]);
                MMA_TF32(o[nt], phi, vh);
                MMA_TF32(o[nt], phi, vl);
                MMA_TF32(o[nt], plo, vh);
            }
        }
        __syncthreads();   // all warps done with Ks/Vs before next tile load
    }

    // ---- Epilogue: normalize, write [B,S,H*HD] ----
    float inv0 = 1.f / l0, inv1 = 1.f / l1;
    int r0 = qb*64 + wm + quad;
    #pragma unroll
    for (int nt = 0; nt < 8; ++nt) {
        int col = nt * 8 + 2 * tq;
        *reinterpret_cast<float2*>(O + base + (size_t)r0 * DIM + col) =
            make_float2(o[nt][0] * inv0, o[nt][1] * inv0);
        *reinterpret_cast<float2*>(O + base + (size_t)(r0 + 8) * DIM + col) =
            make_float2(o[nt][2] * inv1, o[nt][3] * inv1);
    }
}

// ---------------------------------------------------------------------------
extern "C" void kernel_launch(void* const* d_in, const int* in_sizes, int n_in,
                              void* d_out, int out_size)
{
    const float* x  = (const float*)d_in[0];
    const float* Wq = (const float*)d_in[1];
    const float* bq = (const float*)d_in[2];
    const float* Wk = (const float*)d_in[3];
    const float* bk = (const float*)d_in[4];
    const float* Wv = (const float*)d_in[5];
    const float* bv = (const float*)d_in[6];
    const float* Wo = (const float*)d_in[7];
    const float* bo = (const float*)d_in[8];

    float *q, *k, *v, *o;
    cudaGetSymbolAddress((void**)&q, g_q);
    cudaGetSymbolAddress((void**)&k, g_k);
    cudaGetSymbolAddress((void**)&v, g_v);
    cudaGetSymbolAddress((void**)&o, g_o);

    dim3 ggrid(DIM/BN, MTOT/BM);  // (16, 32)

    gemm_tf32_kernel<<<ggrid, 256>>>(x, Wq, bq, q, MTOT, DIM, DIM);
    gemm_tf32_kernel<<<ggrid, 256>>>(x, Wk, bk, k, MTOT, DIM, DIM);
    gemm_tf32_kernel<<<ggrid, 256>>>(x, Wv, bv, v, MTOT, DIM, DIM);

    int smem = (64*KP + 64*VP + 64*KP) * (int)sizeof(float);  // 53248 B
    cudaFuncSetAttribute(attn_mma_kernel, cudaFuncAttributeMaxDynamicSharedMemorySize, smem);
    attn_mma_kernel<<<dim3(SEQ/64, NH, BATCH), 128, smem>>>(q, k, v, o);

    gemm_tf32_kernel<<<ggrid, 256>>>(o, Wo, bo, (float*)d_out, MTOT, DIM, DIM);
}

// round 9
// speedup vs baseline: 1.8510x; 1.1394x over previous
#include <cuda_runtime.h>
#include <math.h>
#include <stdint.h>

#define BATCH 2
#define SEQ   2048
#define DIM   1024
#define NH    16
#define HD    64
#define MTOT  (BATCH*SEQ)   // 4096

// GEMM tiling
#define BM 128
#define BN 64
#define BKC 32
#define KPAD 36

// Attention pads (conflict-free mma fragment patterns)
#define KP 68   // (quad*68 + tq) % 32 all-distinct
#define VP 72   // ((k8+tq)*72 + quad) % 32 all-distinct
#define QTILE 128

// Scratch (allocation-free rule: device globals)
__device__ float g_q[MTOT*DIM];
__device__ float g_k[MTOT*DIM];
__device__ float g_v[MTOT*DIM];
__device__ float g_o[MTOT*DIM];

// ---------------------------------------------------------------------------
// tf32 helpers: 3xTF32 split for ~fp32-accurate tensor-core math
// ---------------------------------------------------------------------------
__device__ __forceinline__ uint32_t f2tf32(float x) {
    uint32_t r;
    asm("cvt.rna.tf32.f32 %0, %1;" : "=r"(r) : "f"(x));
    return r;
}
__device__ __forceinline__ void split_tf32(float x, uint32_t& hi, uint32_t& lo) {
    hi = f2tf32(x);
    lo = f2tf32(x - __uint_as_float(hi));
}
__device__ __forceinline__ void split4(float4 v, uint4& h, uint4& l) {
    split_tf32(v.x, h.x, l.x);
    split_tf32(v.y, h.y, l.y);
    split_tf32(v.z, h.z, l.z);
    split_tf32(v.w, h.w, l.w);
}

#define MMA_TF32(c, a, b)                                                      \
    asm volatile(                                                              \
        "mma.sync.aligned.m16n8k8.row.col.f32.tf32.tf32.f32 "                  \
        "{%0,%1,%2,%3}, {%4,%5,%6,%7}, {%8,%9}, {%0,%1,%2,%3};"                \
        : "+f"((c)[0]), "+f"((c)[1]), "+f"((c)[2]), "+f"((c)[3])               \
        : "r"((a)[0]), "r"((a)[1]), "r"((a)[2]), "r"((a)[3]),                  \
          "r"((b)[0]), "r"((b)[1]))

// ---------------------------------------------------------------------------
// C[M,N] = A[M,K] @ W[N,K]^T + bias[N]   via 3xTF32 mma.sync.
// Pre-split hi/lo planes in smem: inner loop is pure LDS + MMA.
// ---------------------------------------------------------------------------
__global__ __launch_bounds__(256) void gemm_tf32_kernel(
    const float* __restrict__ A, const float* __restrict__ W,
    const float* __restrict__ bias, float* __restrict__ C,
    int M, int N, int K)
{
    extern __shared__ uint32_t smg[];
    uint32_t* Ahi = smg;                   // [BM*KPAD]
    uint32_t* Alo = Ahi + BM*KPAD;
    uint32_t* Bhi = Alo + BM*KPAD;         // [BN*KPAD]
    uint32_t* Blo = Bhi + BN*KPAD;

    const int tid  = threadIdx.x;
    const int wid  = tid >> 5;
    const int lane = tid & 31;
    const int quad = lane >> 2;
    const int tq   = lane & 3;
    const int wm   = (wid & 3) * 32;
    const int wn   = (wid >> 2) * 32;
    const int m0   = blockIdx.y * BM;
    const int n0   = blockIdx.x * BN;

    float c[2][4][4];
    #pragma unroll
    for (int mt = 0; mt < 2; ++mt)
        #pragma unroll
        for (int nt = 0; nt < 4; ++nt)
            #pragma unroll
            for (int r = 0; r < 4; ++r) c[mt][nt][r] = 0.f;

    for (int kt = 0; kt < K; kt += BKC) {
        #pragma unroll
        for (int it = 0; it < 4; ++it) {
            int idx = tid + it * 256;
            int row = idx >> 3;
            int kq  = (idx & 7) << 2;
            float4 a = *reinterpret_cast<const float4*>(A + (size_t)(m0 + row) * K + kt + kq);
            uint4 h, l; split4(a, h, l);
            *reinterpret_cast<uint4*>(Ahi + row * KPAD + kq) = h;
            *reinterpret_cast<uint4*>(Alo + row * KPAD + kq) = l;
        }
        #pragma unroll
        for (int it = 0; it < 2; ++it) {
            int idx = tid + it * 256;
            int row = idx >> 3;
            int kq  = (idx & 7) << 2;
            float4 w = *reinterpret_cast<const float4*>(W + (size_t)(n0 + row) * K + kt + kq);
            uint4 h, l; split4(w, h, l);
            *reinterpret_cast<uint4*>(Bhi + row * KPAD + kq) = h;
            *reinterpret_cast<uint4*>(Blo + row * KPAD + kq) = l;
        }
        __syncthreads();

        #pragma unroll
        for (int kk = 0; kk < BKC; kk += 8) {
            uint32_t ahi[2][4], alo[2][4];
            #pragma unroll
            for (int mt = 0; mt < 2; ++mt) {
                int rb = (wm + mt * 16 + quad) * KPAD + kk + tq;
                ahi[mt][0] = Ahi[rb];              alo[mt][0] = Alo[rb];
                ahi[mt][1] = Ahi[rb + 8*KPAD];     alo[mt][1] = Alo[rb + 8*KPAD];
                ahi[mt][2] = Ahi[rb + 4];          alo[mt][2] = Alo[rb + 4];
                ahi[mt][3] = Ahi[rb + 8*KPAD + 4]; alo[mt][3] = Alo[rb + 8*KPAD + 4];
            }
            uint32_t bhi[4][2], blo[4][2];
            #pragma unroll
            for (int nt = 0; nt < 4; ++nt) {
                int rb = (wn + nt * 8 + quad) * KPAD + kk + tq;
                bhi[nt][0] = Bhi[rb];     blo[nt][0] = Blo[rb];
                bhi[nt][1] = Bhi[rb + 4]; blo[nt][1] = Blo[rb + 4];
            }
            #pragma unroll
            for (int mt = 0; mt < 2; ++mt)
                #pragma unroll
                for (int nt = 0; nt < 4; ++nt) {
                    MMA_TF32(c[mt][nt], ahi[mt], bhi[nt]);
                    MMA_TF32(c[mt][nt], ahi[mt], blo[nt]);
                    MMA_TF32(c[mt][nt], alo[mt], bhi[nt]);
                }
        }
        __syncthreads();
    }

    #pragma unroll
    for (int mt = 0; mt < 2; ++mt) {
        #pragma unroll
        for (int nt = 0; nt < 4; ++nt) {
            int row = m0 + wm + mt * 16 + quad;
            int col = n0 + wn + nt * 8 + tq * 2;
            float bx = bias[col], by = bias[col + 1];
            float2 o0 = make_float2(c[mt][nt][0] + bx, c[mt][nt][1] + by);
            float2 o1 = make_float2(c[mt][nt][2] + bx, c[mt][nt][3] + by);
            *reinterpret_cast<float2*>(C + (size_t)row * N + col)       = o0;
            *reinterpret_cast<float2*>(C + (size_t)(row + 8) * N + col) = o1;
        }
    }
}

// ---------------------------------------------------------------------------
// Causal flash attention via 3xTF32 mma.sync.
// 1 CTA = 256 threads (8 warps) per (128-row q block, head, batch).
// Warp w owns q rows [16w, 16w+16). K/V pre-split into hi/lo tf32 planes
// once per tile (cooperative); inner loops are pure LDS + MMA.
// ---------------------------------------------------------------------------
__global__ __launch_bounds__(256) void attn_mma_kernel(
    const float* __restrict__ Q, const float* __restrict__ Kg,
    const float* __restrict__ Vg, float* __restrict__ O)
{
    extern __shared__ uint32_t smu[];
    uint32_t* Khi = smu;                 // [64*KP]
    uint32_t* Klo = Khi + 64*KP;
    uint32_t* Vhi = Klo + 64*KP;         // [64*VP]
    uint32_t* Vlo = Vhi + 64*VP;
    float*    Ps  = (float*)(Vlo + 64*VP);  // [QTILE*KP] (Q staging, then P)

    const int tid  = threadIdx.x;
    const int wid  = tid >> 5;           // 0..7
    const int lane = tid & 31;
    const int quad = lane >> 2;
    const int tq   = lane & 3;
    const int wm   = wid * 16;           // warp q-row base within 128-row tile

    const int qb = (SEQ/QTILE - 1) - blockIdx.x;   // heavy CTAs first
    const int h  = blockIdx.y;
    const int b  = blockIdx.z;
    const size_t base = ((size_t)b * SEQ) * DIM + (size_t)h * HD;
    const float scale = 0.125f;

    // ---- Stage Q (scaled) into Ps, build per-warp A-frags in registers ----
    #pragma unroll
    for (int it = 0; it < 8; ++it) {
        int idx = tid + it * 256;          // 0..2047
        int row = idx >> 4;                // 0..127
        int kq  = (idx & 15) << 2;         // 0..60
        float4 qv = *reinterpret_cast<const float4*>(Q + base + (size_t)(qb*QTILE + row) * DIM + kq);
        qv.x *= scale; qv.y *= scale; qv.z *= scale; qv.w *= scale;
        *reinterpret_cast<float4*>(Ps + row * KP + kq) = qv;
    }
    __syncthreads();

    uint32_t qhi[8][4], qlo[8][4];
    #pragma unroll
    for (int kt = 0; kt < 8; ++kt) {
        int rb = (wm + quad) * KP + kt * 8 + tq;
        split_tf32(Ps[rb],            qhi[kt][0], qlo[kt][0]);
        split_tf32(Ps[rb + 8*KP],     qhi[kt][1], qlo[kt][1]);
        split_tf32(Ps[rb + 4],        qhi[kt][2], qlo[kt][2]);
        split_tf32(Ps[rb + 8*KP + 4], qhi[kt][3], qlo[kt][3]);
    }
    __syncthreads();

    float o[8][4];
    #pragma unroll
    for (int nt = 0; nt < 8; ++nt)
        #pragma unroll
        for (int r = 0; r < 4; ++r) o[nt][r] = 0.f;
    float m0v = -1e30f, m1v = -1e30f, l0 = 0.f, l1 = 0.f;

    const int nkb = 2 * qb + 2;
    for (int kb = 0; kb < nkb; ++kb) {
        // ---- Load + pre-split K and V tiles (64 keys x 64 dims) ----
        #pragma unroll
        for (int it = 0; it < 4; ++it) {
            int idx = tid + it * 256;
            int row = idx >> 4;            // 0..63
            int kq  = (idx & 15) << 2;
            size_t g = base + (size_t)(kb*64 + row) * DIM + kq;
            float4 kv = *reinterpret_cast<const float4*>(Kg + g);
            uint4 h4, l4; split4(kv, h4, l4);
            *reinterpret_cast<uint4*>(Khi + row * KP + kq) = h4;
            *reinterpret_cast<uint4*>(Klo + row * KP + kq) = l4;
            float4 vv = *reinterpret_cast<const float4*>(Vg + g);
            split4(vv, h4, l4);
            *reinterpret_cast<uint4*>(Vhi + row * VP + kq) = h4;
            *reinterpret_cast<uint4*>(Vlo + row * VP + kq) = l4;
        }
        __syncthreads();

        // ---- S = Qs @ K^T ----
        float s[8][4];
        #pragma unroll
        for (int nt = 0; nt < 8; ++nt)
            #pragma unroll
            for (int r = 0; r < 4; ++r) s[nt][r] = 0.f;

        #pragma unroll
        for (int nt = 0; nt < 8; ++nt) {
            #pragma unroll
            for (int kt = 0; kt < 8; ++kt) {
                int rb = (nt * 8 + quad) * KP + kt * 8 + tq;
                uint32_t bh[2], bl[2];
                bh[0] = Khi[rb];     bl[0] = Klo[rb];
                bh[1] = Khi[rb + 4]; bl[1] = Klo[rb + 4];
                MMA_TF32(s[nt], qhi[kt], bh);
                MMA_TF32(s[nt], qhi[kt], bl);
                MMA_TF32(s[nt], qlo[kt], bh);
            }
        }

        // ---- Causal mask: global col kb*64+c  vs  global row qb*128+r ----
        const int coff = kb * 64 - qb * QTILE;
        if (coff + 63 > 0) {
            int r0 = wm + quad, r1 = r0 + 8;
            #pragma unroll
            for (int nt = 0; nt < 8; ++nt) {
                int c0 = coff + nt * 8 + 2 * tq, c1 = c0 + 1;
                if (c0 > r0) s[nt][0] = -1e30f;
                if (c1 > r0) s[nt][1] = -1e30f;
                if (c0 > r1) s[nt][2] = -1e30f;
                if (c1 > r1) s[nt][3] = -1e30f;
            }
        }

        // ---- Online softmax (rows quad, quad+8; reduce over tq group) ----
        float mx0 = -1e30f, mx1 = -1e30f;
        #pragma unroll
        for (int nt = 0; nt < 8; ++nt) {
            mx0 = fmaxf(mx0, fmaxf(s[nt][0], s[nt][1]));
            mx1 = fmaxf(mx1, fmaxf(s[nt][2], s[nt][3]));
        }
        mx0 = fmaxf(mx0, __shfl_xor_sync(0xffffffffu, mx0, 1));
        mx0 = fmaxf(mx0, __shfl_xor_sync(0xffffffffu, mx0, 2));
        mx1 = fmaxf(mx1, __shfl_xor_sync(0xffffffffu, mx1, 1));
        mx1 = fmaxf(mx1, __shfl_xor_sync(0xffffffffu, mx1, 2));

        float mn0 = fmaxf(m0v, mx0), mn1 = fmaxf(m1v, mx1);
        float c0 = __expf(m0v - mn0), c1 = __expf(m1v - mn1);
        m0v = mn0; m1v = mn1;

        float rs0 = 0.f, rs1 = 0.f;
        #pragma unroll
        for (int nt = 0; nt < 8; ++nt) {
            s[nt][0] = __expf(s[nt][0] - mn0);
            s[nt][1] = __expf(s[nt][1] - mn0);
            s[nt][2] = __expf(s[nt][2] - mn1);
            s[nt][3] = __expf(s[nt][3] - mn1);
            rs0 += s[nt][0] + s[nt][1];
            rs1 += s[nt][2] + s[nt][3];
            *reinterpret_cast<float2*>(Ps + (wm + quad)     * KP + nt*8 + 2*tq) = make_float2(s[nt][0], s[nt][1]);
            *reinterpret_cast<float2*>(Ps + (wm + quad + 8) * KP + nt*8 + 2*tq) = make_float2(s[nt][2], s[nt][3]);
        }
        rs0 += __shfl_xor_sync(0xffffffffu, rs0, 1);
        rs0 += __shfl_xor_sync(0xffffffffu, rs0, 2);
        rs1 += __shfl_xor_sync(0xffffffffu, rs1, 1);
        rs1 += __shfl_xor_sync(0xffffffffu, rs1, 2);
        l0 = l0 * c0 + rs0;
        l1 = l1 * c1 + rs1;

        #pragma unroll
        for (int nt = 0; nt < 8; ++nt) {
            o[nt][0] *= c0; o[nt][1] *= c0;
            o[nt][2] *= c1; o[nt][3] *= c1;
        }
        __syncwarp();   // P rows are warp-private

        // ---- O += P @ V ----
        #pragma unroll
        for (int kt = 0; kt < 8; ++kt) {
            int pb = (wm + quad) * KP + kt * 8 + tq;
            uint32_t phi[4], plo[4];
            split_tf32(Ps[pb],            phi[0], plo[0]);
            split_tf32(Ps[pb + 8*KP],     phi[1], plo[1]);
            split_tf32(Ps[pb + 4],        phi[2], plo[2]);
            split_tf32(Ps[pb + 8*KP + 4], phi[3], plo[3]);
            #pragma unroll
            for (int nt = 0; nt < 8; ++nt) {
                int vb = (kt * 8 + tq) * VP + nt * 8 + quad;
                uint32_t vh[2], vl[2];
                vh[0] = Vhi[vb];          vl[0] = Vlo[vb];
                vh[1] = Vhi[vb + 4*VP];   vl[1] = Vlo[vb + 4*VP];
                MMA_TF32(o[nt], phi, vh);
                MMA_TF32(o[nt], phi, vl);
                MMA_TF32(o[nt], plo, vh);
            }
        }
        __syncthreads();   // Khi/Klo/Vhi/Vlo reused next iteration
    }

    // ---- Epilogue ----
    float inv0 = 1.f / l0, inv1 = 1.f / l1;
    int r0 = qb*QTILE + wm + quad;
    #pragma unroll
    for (int nt = 0; nt < 8; ++nt) {
        int col = nt * 8 + 2 * tq;
        *reinterpret_cast<float2*>(O + base + (size_t)r0 * DIM + col) =
            make_float2(o[nt][0] * inv0, o[nt][1] * inv0);
        *reinterpret_cast<float2*>(O + base + (size_t)(r0 + 8) * DIM + col) =
            make_float2(o[nt][2] * inv1, o[nt][3] * inv1);
    }
}

// ---------------------------------------------------------------------------
extern "C" void kernel_launch(void* const* d_in, const int* in_sizes, int n_in,
                              void* d_out, int out_size)
{
    const float* x  = (const float*)d_in[0];
    const float* Wq = (const float*)d_in[1];
    const float* bq = (const float*)d_in[2];
    const float* Wk = (const float*)d_in[3];
    const float* bk = (const float*)d_in[4];
    const float* Wv = (const float*)d_in[5];
    const float* bv = (const float*)d_in[6];
    const float* Wo = (const float*)d_in[7];
    const float* bo = (const float*)d_in[8];

    float *q, *k, *v, *o;
    cudaGetSymbolAddress((void**)&q, g_q);
    cudaGetSymbolAddress((void**)&k, g_k);
    cudaGetSymbolAddress((void**)&v, g_v);
    cudaGetSymbolAddress((void**)&o, g_o);

    dim3 ggrid(DIM/BN, MTOT/BM);  // (16, 32)
    int gsmem = (2*BM*KPAD + 2*BN*KPAD) * (int)sizeof(uint32_t);   // 55296 B
    cudaFuncSetAttribute(gemm_tf32_kernel, cudaFuncAttributeMaxDynamicSharedMemorySize, gsmem);

    gemm_tf32_kernel<<<ggrid, 256, gsmem>>>(x, Wq, bq, q, MTOT, DIM, DIM);
    gemm_tf32_kernel<<<ggrid, 256, gsmem>>>(x, Wk, bk, k, MTOT, DIM, DIM);
    gemm_tf32_kernel<<<ggrid, 256, gsmem>>>(x, Wv, bv, v, MTOT, DIM, DIM);

    int asmem = (2*64*KP + 2*64*VP + QTILE*KP) * (int)sizeof(uint32_t);  // 106496 B
    cudaFuncSetAttribute(attn_mma_kernel, cudaFuncAttributeMaxDynamicSharedMemorySize, asmem);
    attn_mma_kernel<<<dim3(SEQ/QTILE, NH, BATCH), 256, asmem>>>(q, k, v, o);

    gemm_tf32_kernel<<<ggrid, 256, gsmem>>>(o, Wo, bo, (float*)d_out, MTOT, DIM, DIM);
}

// round 11
// speedup vs baseline: 1.9445x; 1.0506x over previous
#include <cuda_runtime.h>
#include <math.h>
#include <stdint.h>

#define BATCH 2
#define SEQ   2048
#define DIM   1024
#define NH    16
#define HD    64
#define MTOT  (BATCH*SEQ)   // 4096

// GEMM tiling: CTA 128x128, BK=32
#define GBM 128
#define GBN 128
#define GBK 32
#define GKP 36

// Attention pads (conflict-free mma fragment patterns)
#define KP 68
#define VP 72
#define QTILE 128

// Scratch (allocation-free rule: device globals)
__device__ float g_q[MTOT*DIM];
__device__ float g_k[MTOT*DIM];
__device__ float g_v[MTOT*DIM];
__device__ float g_o[MTOT*DIM];

// ---------------------------------------------------------------------------
// tf32 helpers: 3xTF32 split for ~fp32-accurate tensor-core math
// ---------------------------------------------------------------------------
__device__ __forceinline__ uint32_t f2tf32(float x) {
    uint32_t r;
    asm("cvt.rna.tf32.f32 %0, %1;" : "=r"(r) : "f"(x));
    return r;
}
__device__ __forceinline__ void split_tf32(float x, uint32_t& hi, uint32_t& lo) {
    hi = f2tf32(x);
    lo = f2tf32(x - __uint_as_float(hi));
}
__device__ __forceinline__ void split4(float4 v, uint4& h, uint4& l) {
    split_tf32(v.x, h.x, l.x);
    split_tf32(v.y, h.y, l.y);
    split_tf32(v.z, h.z, l.z);
    split_tf32(v.w, h.w, l.w);
}

#define MMA_TF32(c, a, b)                                                      \
    asm volatile(                                                              \
        "mma.sync.aligned.m16n8k8.row.col.f32.tf32.tf32.f32 "                  \
        "{%0,%1,%2,%3}, {%4,%5,%6,%7}, {%8,%9}, {%0,%1,%2,%3};"                \
        : "+f"((c)[0]), "+f"((c)[1]), "+f"((c)[2]), "+f"((c)[3])               \
        : "r"((a)[0]), "r"((a)[1]), "r"((a)[2]), "r"((a)[3]),                  \
          "r"((b)[0]), "r"((b)[1]))

// ---------------------------------------------------------------------------
// C[M,N] = A[M,K] @ W[N,K]^T + bias[N]   via 3xTF32 mma.sync.
// CTA 128x128, 8 warps (4m x 2n), warp tile 32x64.
// Register-staged pipelining: LDG(t+1) issued after barrier, hidden under
// the MMA block of tile t. hi/lo planes pre-split in smem.
// ---------------------------------------------------------------------------
__global__ __launch_bounds__(256) void gemm_tf32_kernel(
    const float* __restrict__ A, const float* __restrict__ W,
    const float* __restrict__ bias, float* __restrict__ C,
    int M, int N, int K)
{
    extern __shared__ uint32_t smg[];
    uint32_t* Ahi = smg;                    // [GBM*GKP]
    uint32_t* Alo = Ahi + GBM*GKP;
    uint32_t* Bhi = Alo + GBM*GKP;          // [GBN*GKP]
    uint32_t* Blo = Bhi + GBN*GKP;

    const int tid  = threadIdx.x;
    const int wid  = tid >> 5;
    const int lane = tid & 31;
    const int quad = lane >> 2;
    const int tq   = lane & 3;
    const int wm   = (wid & 3) * 32;    // 0,32,64,96
    const int wn   = (wid >> 2) * 64;   // 0,64
    const int m0   = blockIdx.y * GBM;
    const int n0   = blockIdx.x * GBN;

    const int ldrow = tid >> 3;          // 0..31 step pattern base
    const int ldkq  = (tid & 7) << 2;

    float c[2][8][4];
    #pragma unroll
    for (int mt = 0; mt < 2; ++mt)
        #pragma unroll
        for (int nt = 0; nt < 8; ++nt)
            #pragma unroll
            for (int r = 0; r < 4; ++r) c[mt][nt][r] = 0.f;

    // register staging buffers (tile t+1 in flight during tile t compute)
    float4 ar[4], br[4];
    #pragma unroll
    for (int it = 0; it < 4; ++it) {
        int row = ldrow + it * 32;
        ar[it] = *reinterpret_cast<const float4*>(A + (size_t)(m0 + row) * K + ldkq);
        br[it] = *reinterpret_cast<const float4*>(W + (size_t)(n0 + row) * K + ldkq);
    }

    for (int kt = 0; kt < K; kt += GBK) {
        // commit staged registers to smem (split hi/lo)
        #pragma unroll
        for (int it = 0; it < 4; ++it) {
            int row = ldrow + it * 32;
            uint4 h, l;
            split4(ar[it], h, l);
            *reinterpret_cast<uint4*>(Ahi + row * GKP + ldkq) = h;
            *reinterpret_cast<uint4*>(Alo + row * GKP + ldkq) = l;
            split4(br[it], h, l);
            *reinterpret_cast<uint4*>(Bhi + row * GKP + ldkq) = h;
            *reinterpret_cast<uint4*>(Blo + row * GKP + ldkq) = l;
        }
        __syncthreads();

        // prefetch next tile into registers (hidden under MMAs below)
        if (kt + GBK < K) {
            #pragma unroll
            for (int it = 0; it < 4; ++it) {
                int row = ldrow + it * 32;
                ar[it] = *reinterpret_cast<const float4*>(A + (size_t)(m0 + row) * K + kt + GBK + ldkq);
                br[it] = *reinterpret_cast<const float4*>(W + (size_t)(n0 + row) * K + kt + GBK + ldkq);
            }
        }

        #pragma unroll
        for (int kk = 0; kk < GBK; kk += 8) {
            uint32_t ahi[2][4], alo[2][4];
            #pragma unroll
            for (int mt = 0; mt < 2; ++mt) {
                int rb = (wm + mt * 16 + quad) * GKP + kk + tq;
                ahi[mt][0] = Ahi[rb];             alo[mt][0] = Alo[rb];
                ahi[mt][1] = Ahi[rb + 8*GKP];     alo[mt][1] = Alo[rb + 8*GKP];
                ahi[mt][2] = Ahi[rb + 4];         alo[mt][2] = Alo[rb + 4];
                ahi[mt][3] = Ahi[rb + 8*GKP + 4]; alo[mt][3] = Alo[rb + 8*GKP + 4];
            }
            #pragma unroll
            for (int nt = 0; nt < 8; ++nt) {
                int rb = (wn + nt * 8 + quad) * GKP + kk + tq;
                uint32_t bh[2], bl[2];
                bh[0] = Bhi[rb];     bl[0] = Blo[rb];
                bh[1] = Bhi[rb + 4]; bl[1] = Blo[rb + 4];
                #pragma unroll
                for (int mt = 0; mt < 2; ++mt) {
                    MMA_TF32(c[mt][nt], ahi[mt], bh);
                    MMA_TF32(c[mt][nt], ahi[mt], bl);
                    MMA_TF32(c[mt][nt], alo[mt], bh);
                }
            }
        }
        __syncthreads();
    }

    #pragma unroll
    for (int mt = 0; mt < 2; ++mt) {
        #pragma unroll
        for (int nt = 0; nt < 8; ++nt) {
            int row = m0 + wm + mt * 16 + quad;
            int col = n0 + wn + nt * 8 + tq * 2;
            float bx = bias[col], by = bias[col + 1];
            float2 o0 = make_float2(c[mt][nt][0] + bx, c[mt][nt][1] + by);
            float2 o1 = make_float2(c[mt][nt][2] + bx, c[mt][nt][3] + by);
            *reinterpret_cast<float2*>(C + (size_t)row * N + col)       = o0;
            *reinterpret_cast<float2*>(C + (size_t)(row + 8) * N + col) = o1;
        }
    }
}

// ---------------------------------------------------------------------------
// Causal flash attention via 3xTF32 mma.sync.
// 1 CTA = 256 threads (8 warps) per (128-row q block, head, batch).
// K/V tiles register-staged (LDG for tile kb+1 issued before tile kb's MMAs),
// then split once into hi/lo smem planes. Inner loops: pure LDS + MMA.
// ---------------------------------------------------------------------------
__global__ __launch_bounds__(256) void attn_mma_kernel(
    const float* __restrict__ Q, const float* __restrict__ Kg,
    const float* __restrict__ Vg, float* __restrict__ O)
{
    extern __shared__ uint32_t smu[];
    uint32_t* Khi = smu;                 // [64*KP]
    uint32_t* Klo = Khi + 64*KP;
    uint32_t* Vhi = Klo + 64*KP;         // [64*VP]
    uint32_t* Vlo = Vhi + 64*VP;
    float*    Ps  = (float*)(Vlo + 64*VP);  // [QTILE*KP] (Q staging, then P)

    const int tid  = threadIdx.x;
    const int wid  = tid >> 5;
    const int lane = tid & 31;
    const int quad = lane >> 2;
    const int tq   = lane & 3;
    const int wm   = wid * 16;

    const int qb = (SEQ/QTILE - 1) - blockIdx.x;   // heavy CTAs first
    const int h  = blockIdx.y;
    const int b  = blockIdx.z;
    const size_t base = ((size_t)b * SEQ) * DIM + (size_t)h * HD;
    const float scale = 0.125f;

    const int ldrow = tid >> 4;          // 0..15 base
    const int ldkq  = (tid & 15) << 2;

    // ---- stage K/V tile 0 into registers ----
    float4 kr[4], vr[4];
    #pragma unroll
    for (int it = 0; it < 4; ++it) {
        int row = ldrow + it * 16;
        size_t g = base + (size_t)row * DIM + ldkq;
        kr[it] = *reinterpret_cast<const float4*>(Kg + g);
        vr[it] = *reinterpret_cast<const float4*>(Vg + g);
    }

    // ---- Stage Q (scaled) into Ps, build per-warp A-frags in registers ----
    #pragma unroll
    for (int it = 0; it < 8; ++it) {
        int idx = tid + it * 256;
        int row = idx >> 4;
        int kq  = (idx & 15) << 2;
        float4 qv = *reinterpret_cast<const float4*>(Q + base + (size_t)(qb*QTILE + row) * DIM + kq);
        qv.x *= scale; qv.y *= scale; qv.z *= scale; qv.w *= scale;
        *reinterpret_cast<float4*>(Ps + row * KP + kq) = qv;
    }
    __syncthreads();

    uint32_t qhi[8][4], qlo[8][4];
    #pragma unroll
    for (int kt = 0; kt < 8; ++kt) {
        int rb = (wm + quad) * KP + kt * 8 + tq;
        split_tf32(Ps[rb],            qhi[kt][0], qlo[kt][0]);
        split_tf32(Ps[rb + 8*KP],     qhi[kt][1], qlo[kt][1]);
        split_tf32(Ps[rb + 4],        qhi[kt][2], qlo[kt][2]);
        split_tf32(Ps[rb + 8*KP + 4], qhi[kt][3], qlo[kt][3]);
    }
    __syncthreads();

    float o[8][4];
    #pragma unroll
    for (int nt = 0; nt < 8; ++nt)
        #pragma unroll
        for (int r = 0; r < 4; ++r) o[nt][r] = 0.f;
    float m0v = -1e30f, m1v = -1e30f, l0 = 0.f, l1 = 0.f;

    const int nkb = 2 * qb + 2;
    for (int kb = 0; kb < nkb; ++kb) {
        // ---- commit staged K/V regs to smem (split hi/lo) ----
        #pragma unroll
        for (int it = 0; it < 4; ++it) {
            int row = ldrow + it * 16;
            uint4 h4, l4;
            split4(kr[it], h4, l4);
            *reinterpret_cast<uint4*>(Khi + row * KP + ldkq) = h4;
            *reinterpret_cast<uint4*>(Klo + row * KP + ldkq) = l4;
            split4(vr[it], h4, l4);
            *reinterpret_cast<uint4*>(Vhi + row * VP + ldkq) = h4;
            *reinterpret_cast<uint4*>(Vlo + row * VP + ldkq) = l4;
        }
        __syncthreads();

        // ---- prefetch next K/V tile into registers ----
        if (kb + 1 < nkb) {
            #pragma unroll
            for (int it = 0; it < 4; ++it) {
                int row = ldrow + it * 16;
                size_t g = base + (size_t)((kb+1)*64 + row) * DIM + ldkq;
                kr[it] = *reinterpret_cast<const float4*>(Kg + g);
                vr[it] = *reinterpret_cast<const float4*>(Vg + g);
            }
        }

        // ---- S = Qs @ K^T ----
        float s[8][4];
        #pragma unroll
        for (int nt = 0; nt < 8; ++nt)
            #pragma unroll
            for (int r = 0; r < 4; ++r) s[nt][r] = 0.f;

        #pragma unroll
        for (int nt = 0; nt < 8; ++nt) {
            #pragma unroll
            for (int kt = 0; kt < 8; ++kt) {
                int rb = (nt * 8 + quad) * KP + kt * 8 + tq;
                uint32_t bh[2], bl[2];
                bh[0] = Khi[rb];     bl[0] = Klo[rb];
                bh[1] = Khi[rb + 4]; bl[1] = Klo[rb + 4];
                MMA_TF32(s[nt], qhi[kt], bh);
                MMA_TF32(s[nt], qhi[kt], bl);
                MMA_TF32(s[nt], qlo[kt], bh);
            }
        }

        // ---- Causal mask ----
        const int coff = kb * 64 - qb * QTILE;
        if (coff + 63 > 0) {
            int r0 = wm + quad, r1 = r0 + 8;
            #pragma unroll
            for (int nt = 0; nt < 8; ++nt) {
                int c0 = coff + nt * 8 + 2 * tq, c1 = c0 + 1;
                if (c0 > r0) s[nt][0] = -1e30f;
                if (c1 > r0) s[nt][1] = -1e30f;
                if (c0 > r1) s[nt][2] = -1e30f;
                if (c1 > r1) s[nt][3] = -1e30f;
            }
        }

        // ---- Online softmax ----
        float mx0 = -1e30f, mx1 = -1e30f;
        #pragma unroll
        for (int nt = 0; nt < 8; ++nt) {
            mx0 = fmaxf(mx0, fmaxf(s[nt][0], s[nt][1]));
            mx1 = fmaxf(mx1, fmaxf(s[nt][2], s[nt][3]));
        }
        mx0 = fmaxf(mx0, __shfl_xor_sync(0xffffffffu, mx0, 1));
        mx0 = fmaxf(mx0, __shfl_xor_sync(0xffffffffu, mx0, 2));
        mx1 = fmaxf(mx1, __shfl_xor_sync(0xffffffffu, mx1, 1));
        mx1 = fmaxf(mx1, __shfl_xor_sync(0xffffffffu, mx1, 2));

        float mn0 = fmaxf(m0v, mx0), mn1 = fmaxf(m1v, mx1);
        float c0 = __expf(m0v - mn0), c1 = __expf(m1v - mn1);
        m0v = mn0; m1v = mn1;

        float rs0 = 0.f, rs1 = 0.f;
        #pragma unroll
        for (int nt = 0; nt < 8; ++nt) {
            s[nt][0] = __expf(s[nt][0] - mn0);
            s[nt][1] = __expf(s[nt][1] - mn0);
            s[nt][2] = __expf(s[nt][2] - mn1);
            s[nt][3] = __expf(s[nt][3] - mn1);
            rs0 += s[nt][0] + s[nt][1];
            rs1 += s[nt][2] + s[nt][3];
            *reinterpret_cast<float2*>(Ps + (wm + quad)     * KP + nt*8 + 2*tq) = make_float2(s[nt][0], s[nt][1]);
            *reinterpret_cast<float2*>(Ps + (wm + quad + 8) * KP + nt*8 + 2*tq) = make_float2(s[nt][2], s[nt][3]);
        }
        rs0 += __shfl_xor_sync(0xffffffffu, rs0, 1);
        rs0 += __shfl_xor_sync(0xffffffffu, rs0, 2);
        rs1 += __shfl_xor_sync(0xffffffffu, rs1, 1);
        rs1 += __shfl_xor_sync(0xffffffffu, rs1, 2);
        l0 = l0 * c0 + rs0;
        l1 = l1 * c1 + rs1;

        #pragma unroll
        for (int nt = 0; nt < 8; ++nt) {
            o[nt][0] *= c0; o[nt][1] *= c0;
            o[nt][2] *= c1; o[nt][3] *= c1;
        }
        __syncwarp();   // P rows are warp-private

        // ---- O += P @ V ----
        #pragma unroll
        for (int kt = 0; kt < 8; ++kt) {
            int pb = (wm + quad) * KP + kt * 8 + tq;
            uint32_t phi[4], plo[4];
            split_tf32(Ps[pb],            phi[0], plo[0]);
            split_tf32(Ps[pb + 8*KP],     phi[1], plo[1]);
            split_tf32(Ps[pb + 4],        phi[2], plo[2]);
            split_tf32(Ps[pb + 8*KP + 4], phi[3], plo[3]);
            #pragma unroll
            for (int nt = 0; nt < 8; ++nt) {
                int vb = (kt * 8 + tq) * VP + nt * 8 + quad;
                uint32_t vh[2], vl[2];
                vh[0] = Vhi[vb];          vl[0] = Vlo[vb];
                vh[1] = Vhi[vb + 4*VP];   vl[1] = Vlo[vb + 4*VP];
                MMA_TF32(o[nt], phi, vh);
                MMA_TF32(o[nt], phi, vl);
                MMA_TF32(o[nt], plo, vh);
            }
        }
        __syncthreads();
    }

    // ---- Epilogue ----
    float inv0 = 1.f / l0, inv1 = 1.f / l1;
    int r0 = qb*QTILE + wm + quad;
    #pragma unroll
    for (int nt = 0; nt < 8; ++nt) {
        int col = nt * 8 + 2 * tq;
        *reinterpret_cast<float2*>(O + base + (size_t)r0 * DIM + col) =
            make_float2(o[nt][0] * inv0, o[nt][1] * inv0);
        *reinterpret_cast<float2*>(O + base + (size_t)(r0 + 8) * DIM + col) =
            make_float2(o[nt][2] * inv1, o[nt][3] * inv1);
    }
}

// ---------------------------------------------------------------------------
extern "C" void kernel_launch(void* const* d_in, const int* in_sizes, int n_in,
                              void* d_out, int out_size)
{
    const float* x  = (const float*)d_in[0];
    const float* Wq = (const float*)d_in[1];
    const float* bq = (const float*)d_in[2];
    const float* Wk = (const float*)d_in[3];
    const float* bk = (const float*)d_in[4];
    const float* Wv = (const float*)d_in[5];
    const float* bv = (const float*)d_in[6];
    const float* Wo = (const float*)d_in[7];
    const float* bo = (const float*)d_in[8];

    float *q, *k, *v, *o;
    cudaGetSymbolAddress((void**)&q, g_q);
    cudaGetSymbolAddress((void**)&k, g_k);
    cudaGetSymbolAddress((void**)&v, g_v);
    cudaGetSymbolAddress((void**)&o, g_o);

    dim3 ggrid(DIM/GBN, MTOT/GBM);  // (8, 32)
    int gsmem = (2*GBM*GKP + 2*GBN*GKP) * (int)sizeof(uint32_t);   // 73728 B
    cudaFuncSetAttribute(gemm_tf32_kernel, cudaFuncAttributeMaxDynamicSharedMemorySize, gsmem);

    gemm_tf32_kernel<<<ggrid, 256, gsmem>>>(x, Wq, bq, q, MTOT, DIM, DIM);
    gemm_tf32_kernel<<<ggrid, 256, gsmem>>>(x, Wk, bk, k, MTOT, DIM, DIM);
    gemm_tf32_kernel<<<ggrid, 256, gsmem>>>(x, Wv, bv, v, MTOT, DIM, DIM);

    int asmem = (2*64*KP + 2*64*VP + QTILE*KP) * (int)sizeof(uint32_t);  // 106496 B
    cudaFuncSetAttribute(attn_mma_kernel, cudaFuncAttributeMaxDynamicSharedMemorySize, asmem);
    attn_mma_kernel<<<dim3(SEQ/QTILE, NH, BATCH), 256, asmem>>>(q, k, v, o);

    gemm_tf32_kernel<<<ggrid, 256, gsmem>>>(o, Wo, bo, (float*)d_out, MTOT, DIM, DIM);
}

// round 12
// speedup vs baseline: 3.2698x; 1.6815x over previous
#include <cuda_runtime.h>
#include <cuda_bf16.h>
#include <math.h>
#include <stdint.h>

#define BATCH 2
#define SEQ   2048
#define DIM   1024
#define NH    16
#define HD    64
#define MTOT  (BATCH*SEQ)   // 4096

// GEMM tiling: CTA 128x128, BK=32 (=16 bf16x2 words), 2-stage double buffer
#define GBM 128
#define GBN 128
#define GBK 32
#define GKW 20                    // padded words/row: (quad*20+tq)%32 all distinct
#define GSTAGE (2*GBM*GKW + 2*GBN*GKW)   // 10240 words per stage

// Attention: 128-row q tile, 64-key k/v tiles, 2-stage double buffer
#define QTILE 128
#define KW 36                     // K plane: 64 rows x (32 words + pad); (quad*36+tq)%32 distinct
#define VW 72                     // V plane: 32 kw-rows x (64 words + pad); (tq*72+quad)%32 distinct
#define QSP 68                    // fp32 Q staging row pitch
#define ASTAGE (2*64*KW + 2*32*VW)       // 9216 words per stage

// Scratch (allocation-free rule: device globals)
__device__ float g_q[MTOT*DIM];
__device__ float g_k[MTOT*DIM];
__device__ float g_v[MTOT*DIM];
__device__ float g_o[MTOT*DIM];

// ---------------------------------------------------------------------------
// bf16 3-term split helpers. Word layout: low 16 bits = lower-k element.
// ---------------------------------------------------------------------------
__device__ __forceinline__ void splitpair(float e0, float e1, uint32_t& h, uint32_t& l) {
    __nv_bfloat16 h0 = __float2bfloat16(e0);
    __nv_bfloat16 h1 = __float2bfloat16(e1);
    __nv_bfloat162 hp = __halves2bfloat162(h0, h1);           // .x = h0 (low)
    h = *reinterpret_cast<uint32_t*>(&hp);
    __nv_bfloat162 lp = __floats2bfloat162_rn(e0 - __bfloat162float(h0),
                                              e1 - __bfloat162float(h1));
    l = *reinterpret_cast<uint32_t*>(&lp);
}
// split a float4 of 4 consecutive k-elements into 2 hi words + 2 lo words
__device__ __forceinline__ void split4k(float4 v, uint2& h, uint2& l) {
    splitpair(v.x, v.y, h.x, l.x);
    splitpair(v.z, v.w, h.y, l.y);
}

#define MMA_BF16(c, a, b)                                                      \
    asm volatile(                                                              \
        "mma.sync.aligned.m16n8k16.row.col.f32.bf16.bf16.f32 "                 \
        "{%0,%1,%2,%3}, {%4,%5,%6,%7}, {%8,%9}, {%0,%1,%2,%3};"                \
        : "+f"((c)[0]), "+f"((c)[1]), "+f"((c)[2]), "+f"((c)[3])               \
        : "r"((a)[0]), "r"((a)[1]), "r"((a)[2]), "r"((a)[3]),                  \
          "r"((b)[0]), "r"((b)[1]))

// ---------------------------------------------------------------------------
// C[M,N] = A[M,K] @ W[N,K]^T + bias[N]   via 3xBF16 m16n8k16 mma.sync.
// CTA 128x128, 8 warps (4m x 2n), warp tile 32x64. 2-stage smem pipeline.
// ---------------------------------------------------------------------------
__global__ __launch_bounds__(256) void gemm_bf16_kernel(
    const float* __restrict__ A, const float* __restrict__ W,
    const float* __restrict__ bias, float* __restrict__ C,
    int M, int N, int K)
{
    extern __shared__ uint32_t smg[];

    const int tid  = threadIdx.x;
    const int wid  = tid >> 5;
    const int lane = tid & 31;
    const int quad = lane >> 2;
    const int tq   = lane & 3;
    const int wm   = (wid & 3) * 32;
    const int wn   = (wid >> 2) * 64;
    const int m0   = blockIdx.y * GBM;
    const int n0   = blockIdx.x * GBN;

    const int ldrow = tid >> 3;          // 0..31 (+32 steps)
    const int ldw   = (tid & 7) * 2;     // word offset 0..14
    const int ldkq  = (tid & 7) * 4;     // float offset 0..28

    float c[2][8][4];
    #pragma unroll
    for (int mt = 0; mt < 2; ++mt)
        #pragma unroll
        for (int nt = 0; nt < 8; ++nt)
            #pragma unroll
            for (int r = 0; r < 4; ++r) c[mt][nt][r] = 0.f;

    float4 ar[4], br[4];
    auto load_regs = [&](int kt) {
        #pragma unroll
        for (int it = 0; it < 4; ++it) {
            int row = ldrow + it * 32;
            ar[it] = *reinterpret_cast<const float4*>(A + (size_t)(m0 + row) * K + kt + ldkq);
            br[it] = *reinterpret_cast<const float4*>(W + (size_t)(n0 + row) * K + kt + ldkq);
        }
    };
    auto store_stage = [&](int s) {
        uint32_t* Ah = smg + s * GSTAGE;
        uint32_t* Al = Ah + GBM*GKW;
        uint32_t* Bh = Al + GBM*GKW;
        uint32_t* Bl = Bh + GBN*GKW;
        #pragma unroll
        for (int it = 0; it < 4; ++it) {
            int row = ldrow + it * 32;
            uint2 h, l;
            split4k(ar[it], h, l);
            *reinterpret_cast<uint2*>(Ah + row * GKW + ldw) = h;
            *reinterpret_cast<uint2*>(Al + row * GKW + ldw) = l;
            split4k(br[it], h, l);
            *reinterpret_cast<uint2*>(Bh + row * GKW + ldw) = h;
            *reinterpret_cast<uint2*>(Bl + row * GKW + ldw) = l;
        }
    };

    load_regs(0);
    store_stage(0);
    __syncthreads();

    int s = 0;
    for (int kt = 0; kt < K; kt += GBK) {
        bool more = (kt + GBK < K);
        if (more) load_regs(kt + GBK);

        uint32_t* Ah = smg + s * GSTAGE;
        uint32_t* Al = Ah + GBM*GKW;
        uint32_t* Bh = Al + GBM*GKW;
        uint32_t* Bl = Bh + GBN*GKW;

        #pragma unroll
        for (int st = 0; st < 2; ++st) {           // 2 k16 steps per 32-k tile
            uint32_t ah[2][4], al[2][4];
            #pragma unroll
            for (int mt = 0; mt < 2; ++mt) {
                int rb = (wm + mt * 16 + quad) * GKW + st * 8 + tq;
                ah[mt][0] = Ah[rb];            al[mt][0] = Al[rb];
                ah[mt][1] = Ah[rb + 8*GKW];    al[mt][1] = Al[rb + 8*GKW];
                ah[mt][2] = Ah[rb + 4];        al[mt][2] = Al[rb + 4];
                ah[mt][3] = Ah[rb + 8*GKW + 4];al[mt][3] = Al[rb + 8*GKW + 4];
            }
            #pragma unroll
            for (int nt = 0; nt < 8; ++nt) {
                int rb = (wn + nt * 8 + quad) * GKW + st * 8 + tq;
                uint32_t bh[2], bl[2];
                bh[0] = Bh[rb];     bl[0] = Bl[rb];
                bh[1] = Bh[rb + 4]; bl[1] = Bl[rb + 4];
                #pragma unroll
                for (int mt = 0; mt < 2; ++mt) {
                    MMA_BF16(c[mt][nt], ah[mt], bh);
                    MMA_BF16(c[mt][nt], ah[mt], bl);
                    MMA_BF16(c[mt][nt], al[mt], bh);
                }
            }
        }
        if (more) store_stage(s ^ 1);
        __syncthreads();
        s ^= 1;
    }

    #pragma unroll
    for (int mt = 0; mt < 2; ++mt) {
        #pragma unroll
        for (int nt = 0; nt < 8; ++nt) {
            int row = m0 + wm + mt * 16 + quad;
            int col = n0 + wn + nt * 8 + tq * 2;
            float bx = bias[col], by = bias[col + 1];
            float2 o0 = make_float2(c[mt][nt][0] + bx, c[mt][nt][1] + by);
            float2 o1 = make_float2(c[mt][nt][2] + bx, c[mt][nt][3] + by);
            *reinterpret_cast<float2*>(C + (size_t)row * N + col)       = o0;
            *reinterpret_cast<float2*>(C + (size_t)(row + 8) * N + col) = o1;
        }
    }
}

// ---------------------------------------------------------------------------
// Causal flash attention via 3xBF16 m16n8k16 mma.sync.
// 256 threads (8 warps) per (128-row q block, head, batch).
// K plane: [key][packed-dims]; V plane: [kw=key/2][dims] (pairs across keys).
// P stays entirely in registers (exp outputs are already the PV A-fragment).
// 2-stage K/V double buffer; Q staged fp32 once (overlaying stage 0).
// ---------------------------------------------------------------------------
__global__ __launch_bounds__(256) void attn_mma_kernel(
    const float* __restrict__ Q, const float* __restrict__ Kg,
    const float* __restrict__ Vg, float* __restrict__ O)
{
    extern __shared__ uint32_t smu[];

    const int tid  = threadIdx.x;
    const int wid  = tid >> 5;
    const int lane = tid & 31;
    const int quad = lane >> 2;
    const int tq   = lane & 3;
    const int wm   = wid * 16;

    const int qb = (SEQ/QTILE - 1) - blockIdx.x;   // heavy CTAs first
    const int h  = blockIdx.y;
    const int b  = blockIdx.z;
    const size_t base = ((size_t)b * SEQ) * DIM + (size_t)h * HD;
    const float scale = 0.125f;

    const int lr  = tid >> 4;            // 0..15
    const int lfq = tid & 15;            // float4 slot 0..15 (dims lfq*4)

    float4 kr[4], vr[4];
    auto load_kv_regs = [&](int kb) {
        #pragma unroll
        for (int it = 0; it < 4; ++it) {     // K: rows 0..63
            int row = lr + it * 16;
            kr[it] = *reinterpret_cast<const float4*>(Kg + base + (size_t)(kb*64 + row) * DIM + lfq*4);
        }
        #pragma unroll
        for (int it = 0; it < 2; ++it) {     // V: key pairs (2kw, 2kw+1)
            int kw = lr + it * 16;
            vr[2*it]   = *reinterpret_cast<const float4*>(Vg + base + (size_t)(kb*64 + 2*kw)   * DIM + lfq*4);
            vr[2*it+1] = *reinterpret_cast<const float4*>(Vg + base + (size_t)(kb*64 + 2*kw+1) * DIM + lfq*4);
        }
    };
    auto store_kv = [&](int s) {
        uint32_t* Kh = smu + s * ASTAGE;
        uint32_t* Kl = Kh + 64*KW;
        uint32_t* Vh = Kl + 64*KW;
        uint32_t* Vl = Vh + 32*VW;
        #pragma unroll
        for (int it = 0; it < 4; ++it) {
            int row = lr + it * 16;
            uint2 h2, l2;
            split4k(kr[it], h2, l2);
            *reinterpret_cast<uint2*>(Kh + row * KW + lfq*2) = h2;
            *reinterpret_cast<uint2*>(Kl + row * KW + lfq*2) = l2;
        }
        #pragma unroll
        for (int it = 0; it < 2; ++it) {
            int kw = lr + it * 16;
            float e0[4] = {vr[2*it].x, vr[2*it].y, vr[2*it].z, vr[2*it].w};
            float e1[4] = {vr[2*it+1].x, vr[2*it+1].y, vr[2*it+1].z, vr[2*it+1].w};
            uint4 h4, l4;
            splitpair(e0[0], e1[0], h4.x, l4.x);
            splitpair(e0[1], e1[1], h4.y, l4.y);
            splitpair(e0[2], e1[2], h4.z, l4.z);
            splitpair(e0[3], e1[3], h4.w, l4.w);
            *reinterpret_cast<uint4*>(Vh + kw * VW + lfq*4) = h4;
            *reinterpret_cast<uint4*>(Vl + kw * VW + lfq*4) = l4;
        }
    };

    // ---- prologue: LDG tile 0, stage Q (fp32) into stage-0 area ----
    load_kv_regs(0);
    float* Qs = (float*)smu;
    #pragma unroll
    for (int it = 0; it < 8; ++it) {
        int idx = tid + it * 256;
        int row = idx >> 4;
        int kq  = (idx & 15) << 2;
        float4 qv = *reinterpret_cast<const float4*>(Q + base + (size_t)(qb*QTILE + row) * DIM + kq);
        qv.x *= scale; qv.y *= scale; qv.z *= scale; qv.w *= scale;
        *reinterpret_cast<float4*>(Qs + row * QSP + kq) = qv;
    }
    __syncthreads();

    uint32_t qh[4][4], ql[4][4];
    #pragma unroll
    for (int st = 0; st < 4; ++st) {      // 4 k16 steps over 64 dims
        const float* r0 = Qs + (wm + quad) * QSP + st * 16 + 2 * tq;
        const float* r1 = r0 + 8 * QSP;
        float2 p;
        p = *reinterpret_cast<const float2*>(r0);     splitpair(p.x, p.y, qh[st][0], ql[st][0]);
        p = *reinterpret_cast<const float2*>(r1);     splitpair(p.x, p.y, qh[st][1], ql[st][1]);
        p = *reinterpret_cast<const float2*>(r0 + 8); splitpair(p.x, p.y, qh[st][2], ql[st][2]);
        p = *reinterpret_cast<const float2*>(r1 + 8); splitpair(p.x, p.y, qh[st][3], ql[st][3]);
    }
    __syncthreads();

    store_kv(0);
    __syncthreads();

    float o[8][4];
    #pragma unroll
    for (int nt = 0; nt < 8; ++nt)
        #pragma unroll
        for (int r = 0; r < 4; ++r) o[nt][r] = 0.f;
    float m0v = -1e30f, m1v = -1e30f, l0 = 0.f, l1 = 0.f;

    const int nkb = 2 * qb + 2;
    int s = 0;
    for (int kb = 0; kb < nkb; ++kb) {
        bool more = (kb + 1 < nkb);
        if (more) load_kv_regs(kb + 1);

        uint32_t* Kh = smu + s * ASTAGE;
        uint32_t* Kl = Kh + 64*KW;
        uint32_t* Vh = Kl + 64*KW;
        uint32_t* Vl = Vh + 32*VW;

        // ---- S = Qs @ K^T ----
        float sv[8][4];
        #pragma unroll
        for (int nt = 0; nt < 8; ++nt)
            #pragma unroll
            for (int r = 0; r < 4; ++r) sv[nt][r] = 0.f;

        #pragma unroll
        for (int nt = 0; nt < 8; ++nt) {
            #pragma unroll
            for (int st = 0; st < 4; ++st) {
                int rb = (nt * 8 + quad) * KW + st * 8 + tq;
                uint32_t bh[2], bl[2];
                bh[0] = Kh[rb];     bl[0] = Kl[rb];
                bh[1] = Kh[rb + 4]; bl[1] = Kl[rb + 4];
                MMA_BF16(sv[nt], qh[st], bh);
                MMA_BF16(sv[nt], qh[st], bl);
                MMA_BF16(sv[nt], ql[st], bh);
            }
        }

        // ---- Causal mask ----
        const int coff = kb * 64 - qb * QTILE;
        if (coff + 63 > 0) {
            int r0 = wm + quad, r1 = r0 + 8;
            #pragma unroll
            for (int nt = 0; nt < 8; ++nt) {
                int c0 = coff + nt * 8 + 2 * tq, c1 = c0 + 1;
                if (c0 > r0) sv[nt][0] = -1e30f;
                if (c1 > r0) sv[nt][1] = -1e30f;
                if (c0 > r1) sv[nt][2] = -1e30f;
                if (c1 > r1) sv[nt][3] = -1e30f;
            }
        }

        // ---- Online softmax ----
        float mx0 = -1e30f, mx1 = -1e30f;
        #pragma unroll
        for (int nt = 0; nt < 8; ++nt) {
            mx0 = fmaxf(mx0, fmaxf(sv[nt][0], sv[nt][1]));
            mx1 = fmaxf(mx1, fmaxf(sv[nt][2], sv[nt][3]));
        }
        mx0 = fmaxf(mx0, __shfl_xor_sync(0xffffffffu, mx0, 1));
        mx0 = fmaxf(mx0, __shfl_xor_sync(0xffffffffu, mx0, 2));
        mx1 = fmaxf(mx1, __shfl_xor_sync(0xffffffffu, mx1, 1));
        mx1 = fmaxf(mx1, __shfl_xor_sync(0xffffffffu, mx1, 2));

        float mn0 = fmaxf(m0v, mx0), mn1 = fmaxf(m1v, mx1);
        float c0 = __expf(m0v - mn0), c1 = __expf(m1v - mn1);
        m0v = mn0; m1v = mn1;

        float rs0 = 0.f, rs1 = 0.f;
        #pragma unroll
        for (int nt = 0; nt < 8; ++nt) {
            sv[nt][0] = __expf(sv[nt][0] - mn0);
            sv[nt][1] = __expf(sv[nt][1] - mn0);
            sv[nt][2] = __expf(sv[nt][2] - mn1);
            sv[nt][3] = __expf(sv[nt][3] - mn1);
            rs0 += sv[nt][0] + sv[nt][1];
            rs1 += sv[nt][2] + sv[nt][3];
        }
        rs0 += __shfl_xor_sync(0xffffffffu, rs0, 1);
        rs0 += __shfl_xor_sync(0xffffffffu, rs0, 2);
        rs1 += __shfl_xor_sync(0xffffffffu, rs1, 1);
        rs1 += __shfl_xor_sync(0xffffffffu, rs1, 2);
        l0 = l0 * c0 + rs0;
        l1 = l1 * c1 + rs1;

        #pragma unroll
        for (int nt = 0; nt < 8; ++nt) {
            o[nt][0] *= c0; o[nt][1] *= c0;
            o[nt][2] *= c1; o[nt][3] *= c1;
        }

        // ---- O += P @ V  (P packed from registers; no smem round trip) ----
        #pragma unroll
        for (int kt = 0; kt < 4; ++kt) {
            uint32_t ph[4], pl[4];
            splitpair(sv[2*kt][0],   sv[2*kt][1],   ph[0], pl[0]);
            splitpair(sv[2*kt][2],   sv[2*kt][3],   ph[1], pl[1]);
            splitpair(sv[2*kt+1][0], sv[2*kt+1][1], ph[2], pl[2]);
            splitpair(sv[2*kt+1][2], sv[2*kt+1][3], ph[3], pl[3]);
            #pragma unroll
            for (int nt = 0; nt < 8; ++nt) {
                int vb = (kt * 8 + tq) * VW + nt * 8 + quad;
                uint32_t vh[2], vl[2];
                vh[0] = Vh[vb];          vl[0] = Vl[vb];
                vh[1] = Vh[vb + 4*VW];   vl[1] = Vl[vb + 4*VW];
                MMA_BF16(o[nt], ph, vh);
                MMA_BF16(o[nt], ph, vl);
                MMA_BF16(o[nt], pl, vh);
            }
        }

        if (more) store_kv(s ^ 1);
        __syncthreads();
        s ^= 1;
    }

    // ---- Epilogue ----
    float inv0 = 1.f / l0, inv1 = 1.f / l1;
    int r0 = qb*QTILE + wm + quad;
    #pragma unroll
    for (int nt = 0; nt < 8; ++nt) {
        int col = nt * 8 + 2 * tq;
        *reinterpret_cast<float2*>(O + base + (size_t)r0 * DIM + col) =
            make_float2(o[nt][0] * inv0, o[nt][1] * inv0);
        *reinterpret_cast<float2*>(O + base + (size_t)(r0 + 8) * DIM + col) =
            make_float2(o[nt][2] * inv1, o[nt][3] * inv1);
    }
}

// ---------------------------------------------------------------------------
extern "C" void kernel_launch(void* const* d_in, const int* in_sizes, int n_in,
                              void* d_out, int out_size)
{
    const float* x  = (const float*)d_in[0];
    const float* Wq = (const float*)d_in[1];
    const float* bq = (const float*)d_in[2];
    const float* Wk = (const float*)d_in[3];
    const float* bk = (const float*)d_in[4];
    const float* Wv = (const float*)d_in[5];
    const float* bv = (const float*)d_in[6];
    const float* Wo = (const float*)d_in[7];
    const float* bo = (const float*)d_in[8];

    float *q, *k, *v, *o;
    cudaGetSymbolAddress((void**)&q, g_q);
    cudaGetSymbolAddress((void**)&k, g_k);
    cudaGetSymbolAddress((void**)&v, g_v);
    cudaGetSymbolAddress((void**)&o, g_o);

    dim3 ggrid(DIM/GBN, MTOT/GBM);  // (8, 32)
    int gsmem = 2 * GSTAGE * (int)sizeof(uint32_t);   // 81920 B
    cudaFuncSetAttribute(gemm_bf16_kernel, cudaFuncAttributeMaxDynamicSharedMemorySize, gsmem);

    gemm_bf16_kernel<<<ggrid, 256, gsmem>>>(x, Wq, bq, q, MTOT, DIM, DIM);
    gemm_bf16_kernel<<<ggrid, 256, gsmem>>>(x, Wk, bk, k, MTOT, DIM, DIM);
    gemm_bf16_kernel<<<ggrid, 256, gsmem>>>(x, Wv, bv, v, MTOT, DIM, DIM);

    int asmem = 2 * ASTAGE * (int)sizeof(uint32_t);   // 73728 B
    cudaFuncSetAttribute(attn_mma_kernel, cudaFuncAttributeMaxDynamicSharedMemorySize, asmem);
    attn_mma_kernel<<<dim3(SEQ/QTILE, NH, BATCH), 256, asmem>>>(q, k, v, o);

    gemm_bf16_kernel<<<ggrid, 256, gsmem>>>(o, Wo, bo, (float*)d_out, MTOT, DIM, DIM);
}

// round 14
// speedup vs baseline: 3.7024x; 1.1323x over previous
#include <cuda_runtime.h>
#include <cuda_bf16.h>
#include <stdint.h>

#define BATCH 2
#define SEQ   2048
#define DIM   1024
#define NH    16
#define HD    64
#define MTOT  (BATCH*SEQ)   // 4096

// GEMM: CTA 128x128x32, 2-stage cp.async pipeline
#define GBM 128
#define GBN 128
#define GBK 32
#define GPB  80                 // smem row pitch bytes (32 bf16 data + 16B pad): (5r)%8 distinct
#define APLB (GBM*GPB)          // plane bytes 10240
#define GSTAGEB (4*APLB)        // Ah,Al,Bh,Bl = 40960 B

// Attention: 128-row q tile, 64-key kv tiles, 2-stage cp.async
#define QT 128
#define APB  144                // kv plane row pitch bytes (64 bf16 + 16B pad): r%8 distinct
#define KPLB (64*APB)           // 9216 B per plane
#define ASTAGEB (4*KPLB)        // Kh,Kl,Vh,Vl = 36864 B

// bf16 hi/lo planes (allocation-free rule: device globals)
__device__ __nv_bfloat16 g_xh[MTOT*DIM], g_xl[MTOT*DIM];
__device__ __nv_bfloat16 g_wh[4*DIM*DIM], g_wl[4*DIM*DIM];
__device__ __nv_bfloat16 g_qh[MTOT*DIM], g_ql[MTOT*DIM];
__device__ __nv_bfloat16 g_kh[MTOT*DIM], g_kl[MTOT*DIM];
__device__ __nv_bfloat16 g_vh[MTOT*DIM], g_vl[MTOT*DIM];
__device__ __nv_bfloat16 g_oh[MTOT*DIM], g_ol[MTOT*DIM];

// ---------------------------------------------------------------------------
__device__ __forceinline__ void splitpair(float e0, float e1, uint32_t& h, uint32_t& l) {
    __nv_bfloat16 h0 = __float2bfloat16(e0);
    __nv_bfloat16 h1 = __float2bfloat16(e1);
    __nv_bfloat162 hp = __halves2bfloat162(h0, h1);
    h = *reinterpret_cast<uint32_t*>(&hp);
    __nv_bfloat162 lp = __floats2bfloat162_rn(e0 - __bfloat162float(h0),
                                              e1 - __bfloat162float(h1));
    l = *reinterpret_cast<uint32_t*>(&lp);
}
__device__ __forceinline__ void split4k(float4 v, uint2& h, uint2& l) {
    splitpair(v.x, v.y, h.x, l.x);
    splitpair(v.z, v.w, h.y, l.y);
}

#define MMA_BF16(c, a, b)                                                      \
    asm volatile(                                                              \
        "mma.sync.aligned.m16n8k16.row.col.f32.bf16.bf16.f32 "                 \
        "{%0,%1,%2,%3}, {%4,%5,%6,%7}, {%8,%9}, {%0,%1,%2,%3};"                \
        : "+f"((c)[0]), "+f"((c)[1]), "+f"((c)[2]), "+f"((c)[3])               \
        : "r"((a)[0]), "r"((a)[1]), "r"((a)[2]), "r"((a)[3]),                  \
          "r"((b)[0]), "r"((b)[1]))

__device__ __forceinline__ void ldm_x4(uint32_t* r, uint32_t a) {
    asm volatile("ldmatrix.sync.aligned.m8n8.x4.shared.b16 {%0,%1,%2,%3}, [%4];"
        : "=r"(r[0]), "=r"(r[1]), "=r"(r[2]), "=r"(r[3]) : "r"(a));
}
__device__ __forceinline__ void ldm_x4t(uint32_t* r, uint32_t a) {
    asm volatile("ldmatrix.sync.aligned.m8n8.x4.trans.shared.b16 {%0,%1,%2,%3}, [%4];"
        : "=r"(r[0]), "=r"(r[1]), "=r"(r[2]), "=r"(r[3]) : "r"(a));
}
__device__ __forceinline__ void cp16(uint32_t s, const void* g) {
    asm volatile("cp.async.cg.shared.global [%0], [%1], 16;" :: "r"(s), "l"(g));
}
#define CP_COMMIT() asm volatile("cp.async.commit_group;")
#define CP_WAIT0()  asm volatile("cp.async.wait_group 0;")

// ---------------------------------------------------------------------------
// Prep: fp32 -> bf16 hi/lo planes
// ---------------------------------------------------------------------------
__global__ void split_planes_kernel(const float* __restrict__ src,
    __nv_bfloat16* __restrict__ h, __nv_bfloat16* __restrict__ l, int n4)
{
    int i = blockIdx.x * blockDim.x + threadIdx.x;
    if (i < n4) {
        float4 v = reinterpret_cast<const float4*>(src)[i];
        uint2 hw, lw; split4k(v, hw, lw);
        reinterpret_cast<uint2*>(h)[i] = hw;
        reinterpret_cast<uint2*>(l)[i] = lw;
    }
}

// ---------------------------------------------------------------------------
// GEMM C[M,N] = A[M,K] @ W[N,K]^T (+bias) via 3xBF16 mma.sync on hi/lo planes.
// MODE 0: out = bf16 hi/lo planes of (acc+bias)*scale, grid.z selects q/k/v.
// MODE 1: out = fp32 (acc+bias).
// ---------------------------------------------------------------------------
template<int MODE>
__global__ __launch_bounds__(256, 2) void gemm_planes_kernel(
    const __nv_bfloat16* __restrict__ Ah, const __nv_bfloat16* __restrict__ Al,
    const __nv_bfloat16* __restrict__ Wh, const __nv_bfloat16* __restrict__ Wl,
    const float* __restrict__ bq, const float* __restrict__ bk, const float* __restrict__ bv,
    uint32_t* __restrict__ oh0, uint32_t* __restrict__ ol0,
    uint32_t* __restrict__ oh1, uint32_t* __restrict__ ol1,
    uint32_t* __restrict__ oh2, uint32_t* __restrict__ ol2,
    float* __restrict__ Cf)
{
    extern __shared__ char smc[];
    const uint32_t smb = (uint32_t)__cvta_generic_to_shared(smc);
    const int tid = threadIdx.x, wid = tid >> 5, lane = tid & 31;
    const int quad = lane >> 2, tq = lane & 3;
    const int wm = (wid & 3) * 32, wn = (wid >> 2) * 64;
    const int m0 = blockIdx.y * GBM, n0 = blockIdx.x * GBN;
    const int z  = blockIdx.z;
    const __nv_bfloat16* Bh = Wh + (size_t)z * DIM * DIM;
    const __nv_bfloat16* Bl = Wl + (size_t)z * DIM * DIM;
    const float* bias = (MODE == 1) ? bq : (z == 0 ? bq : z == 1 ? bk : bv);

    const int crow = tid >> 2, cch = (tid & 3) * 8;   // cp.async: row, chunk elem offset
    const int a_ro = ((lane >> 3) & 1) * 8 + (lane & 7);
    const int a_kb = ((lane >> 4) & 1) * 16;
    const int b_ro = (lane & 7) + ((lane >> 4) & 1) * 8;
    const int b_kb = ((lane >> 3) & 1) * 16;

    float c[2][8][4] = {};

    auto stage_load = [&](int s, int kt) {
        uint32_t sb = smb + s * GSTAGEB;
        #pragma unroll
        for (int i = 0; i < 2; ++i) {
            int r = crow + i * 64;
            size_t ga = (size_t)(m0 + r) * DIM + kt + cch;
            cp16(sb +            r * GPB + cch * 2, Ah + ga);
            cp16(sb +   APLB +   r * GPB + cch * 2, Al + ga);
            size_t gb = (size_t)(n0 + r) * DIM + kt + cch;
            cp16(sb + 2*APLB +   r * GPB + cch * 2, Bh + gb);
            cp16(sb + 3*APLB +   r * GPB + cch * 2, Bl + gb);
        }
        CP_COMMIT();
    };

    stage_load(0, 0);
    int s = 0;
    #pragma unroll 1
    for (int it = 0; it < DIM / GBK; ++it) {
        CP_WAIT0();
        __syncthreads();
        if (it + 1 < DIM / GBK) stage_load(s ^ 1, (it + 1) * GBK);

        uint32_t ab = smb + s * GSTAGEB;
        #pragma unroll
        for (int st = 0; st < 2; ++st) {
            uint32_t ah[2][4], al2[2][4];
            #pragma unroll
            for (int mt = 0; mt < 2; ++mt) {
                uint32_t aa = ab + (wm + mt * 16 + a_ro) * GPB + st * 32 + a_kb;
                ldm_x4(ah[mt], aa);
                ldm_x4(al2[mt], aa + APLB);
            }
            #pragma unroll
            for (int np = 0; np < 4; ++np) {
                uint32_t ba = ab + 2*APLB + (wn + np * 16 + b_ro) * GPB + st * 32 + b_kb;
                uint32_t bh4[4], bl4[4];
                ldm_x4(bh4, ba);
                ldm_x4(bl4, ba + APLB);
                #pragma unroll
                for (int hf = 0; hf < 2; ++hf) {
                    int nt = np * 2 + hf;
                    uint32_t b2h[2] = {bh4[hf*2], bh4[hf*2+1]};
                    uint32_t b2l[2] = {bl4[hf*2], bl4[hf*2+1]};
                    #pragma unroll
                    for (int mt = 0; mt < 2; ++mt) {
                        MMA_BF16(c[mt][nt], ah[mt],  b2h);
                        MMA_BF16(c[mt][nt], ah[mt],  b2l);
                        MMA_BF16(c[mt][nt], al2[mt], b2h);
                    }
                }
            }
        }
        s ^= 1;
    }

    if (MODE == 1) {
        #pragma unroll
        for (int mt = 0; mt < 2; ++mt)
            #pragma unroll
            for (int nt = 0; nt < 8; ++nt) {
                int row = m0 + wm + mt * 16 + quad;
                int col = n0 + wn + nt * 8 + tq * 2;
                float bx = bias[col], by = bias[col + 1];
                *reinterpret_cast<float2*>(Cf + (size_t)row * DIM + col) =
                    make_float2(c[mt][nt][0] + bx, c[mt][nt][1] + by);
                *reinterpret_cast<float2*>(Cf + (size_t)(row + 8) * DIM + col) =
                    make_float2(c[mt][nt][2] + bx, c[mt][nt][3] + by);
            }
    } else {
        float scale = (z == 0) ? 0.125f : 1.0f;
        uint32_t* oh = z == 0 ? oh0 : z == 1 ? oh1 : oh2;
        uint32_t* ol = z == 0 ? ol0 : z == 1 ? ol1 : ol2;
        #pragma unroll
        for (int mt = 0; mt < 2; ++mt)
            #pragma unroll
            for (int nt = 0; nt < 8; ++nt) {
                int row = m0 + wm + mt * 16 + quad;
                int col = n0 + wn + nt * 8 + tq * 2;
                float bx = bias[col], by = bias[col + 1];
                uint32_t hw, lw;
                splitpair((c[mt][nt][0] + bx) * scale, (c[mt][nt][1] + by) * scale, hw, lw);
                size_t w0 = ((size_t)row * DIM + col) >> 1;
                oh[w0] = hw; ol[w0] = lw;
                splitpair((c[mt][nt][2] + bx) * scale, (c[mt][nt][3] + by) * scale, hw, lw);
                size_t w1 = ((size_t)(row + 8) * DIM + col) >> 1;
                oh[w1] = hw; ol[w1] = lw;
            }
    }
}

// ---------------------------------------------------------------------------
// Causal flash attention, 3xBF16 mma.sync on pre-split planes.
// 256 threads per (128-row q block, head, batch). cp.async 2-stage K/V;
// ldmatrix frags (trans for V); Q frags direct from gmem planes; P in regs.
// ---------------------------------------------------------------------------
__global__ __launch_bounds__(256, 1) void attn_mma_kernel(
    const __nv_bfloat16* __restrict__ Qh, const __nv_bfloat16* __restrict__ Ql,
    const __nv_bfloat16* __restrict__ Kh, const __nv_bfloat16* __restrict__ Kl,
    const __nv_bfloat16* __restrict__ Vh, const __nv_bfloat16* __restrict__ Vl,
    uint32_t* __restrict__ Oh, uint32_t* __restrict__ Ol)
{
    extern __shared__ char smc[];
    const uint32_t smb = (uint32_t)__cvta_generic_to_shared(smc);
    const int tid = threadIdx.x, wid = tid >> 5, lane = tid & 31;
    const int quad = lane >> 2, tq = lane & 3;
    const int wm = wid * 16;

    const int qb = (SEQ / QT - 1) - blockIdx.x;    // heavy CTAs first
    const int h  = blockIdx.y;
    const int b  = blockIdx.z;
    const size_t base  = ((size_t)b * SEQ) * DIM + (size_t)h * HD;
    const size_t wbase = base >> 1;

    const int crow = tid >> 3, cch = (tid & 7) * 8;
    auto load_kv = [&](int s, int kb) {
        uint32_t sb = smb + s * ASTAGEB;
        #pragma unroll
        for (int i = 0; i < 2; ++i) {
            int r = crow + i * 32;
            size_t g = base + (size_t)(kb * 64 + r) * DIM + cch;
            cp16(sb +            r * APB + cch * 2, Kh + g);
            cp16(sb +   KPLB +   r * APB + cch * 2, Kl + g);
            cp16(sb + 2*KPLB +   r * APB + cch * 2, Vh + g);
            cp16(sb + 3*KPLB +   r * APB + cch * 2, Vl + g);
        }
        CP_COMMIT();
    };

    load_kv(0, 0);

    // Q fragments straight from gmem planes (prologue only)
    const uint32_t* Qh32 = (const uint32_t*)Qh;
    const uint32_t* Ql32 = (const uint32_t*)Ql;
    uint32_t qh[4][4], ql[4][4];
    {
        size_t r0w = wbase + (size_t)(qb * QT + wm + quad) * (DIM / 2);
        size_t r1w = r0w + 8 * (DIM / 2);
        #pragma unroll
        for (int st = 0; st < 4; ++st) {
            int w0 = st * 8 + tq;
            qh[st][0] = Qh32[r0w + w0];     ql[st][0] = Ql32[r0w + w0];
            qh[st][1] = Qh32[r1w + w0];     ql[st][1] = Ql32[r1w + w0];
            qh[st][2] = Qh32[r0w + w0 + 4]; ql[st][2] = Ql32[r0w + w0 + 4];
            qh[st][3] = Qh32[r1w + w0 + 4]; ql[st][3] = Ql32[r1w + w0 + 4];
        }
    }

    const int k_ro = (lane & 7) + ((lane >> 4) & 1) * 8;   // K non-trans
    const int k_kb = ((lane >> 3) & 1) * 16;
    const int v_ro = (lane & 7) + ((lane >> 3) & 1) * 8;   // V trans
    const int v_db = ((lane >> 4) & 1) * 16;

    float o[8][4] = {};
    float m0v = -1e30f, m1v = -1e30f, l0 = 0.f, l1 = 0.f;

    const int nkb = 2 * qb + 2;
    int s = 0;
    #pragma unroll 1
    for (int kb = 0; kb < nkb; ++kb) {
        CP_WAIT0();
        __syncthreads();
        if (kb + 1 < nkb) load_kv(s ^ 1, kb + 1);

        uint32_t kbh = smb + s * ASTAGEB;
        uint32_t vbh = kbh + 2 * KPLB;

        // ---- S = Q @ K^T ----
        float sv[8][4] = {};
        #pragma unroll
        for (int st = 0; st < 4; ++st) {
            #pragma unroll
            for (int np = 0; np < 4; ++np) {
                uint32_t ba = kbh + (np * 16 + k_ro) * APB + st * 32 + k_kb;
                uint32_t bh4[4], bl4[4];
                ldm_x4(bh4, ba);
                ldm_x4(bl4, ba + KPLB);
                #pragma unroll
                for (int hf = 0; hf < 2; ++hf) {
                    int nt = np * 2 + hf;
                    uint32_t b2h[2] = {bh4[hf*2], bh4[hf*2+1]};
                    uint32_t b2l[2] = {bl4[hf*2], bl4[hf*2+1]};
                    MMA_BF16(sv[nt], qh[st], b2h);
                    MMA_BF16(sv[nt], qh[st], b2l);
                    MMA_BF16(sv[nt], ql[st], b2h);
                }
            }
        }

        // ---- Causal mask ----
        const int coff = kb * 64 - qb * QT;
        if (coff + 63 > 0) {
            int r0 = wm + quad, r1 = r0 + 8;
            #pragma unroll
            for (int nt = 0; nt < 8; ++nt) {
                int c0 = coff + nt * 8 + 2 * tq, c1 = c0 + 1;
                if (c0 > r0) sv[nt][0] = -1e30f;
                if (c1 > r0) sv[nt][1] = -1e30f;
                if (c0 > r1) sv[nt][2] = -1e30f;
                if (c1 > r1) sv[nt][3] = -1e30f;
            }
        }

        // ---- Online softmax ----
        float mx0 = -1e30f, mx1 = -1e30f;
        #pragma unroll
        for (int nt = 0; nt < 8; ++nt) {
            mx0 = fmaxf(mx0, fmaxf(sv[nt][0], sv[nt][1]));
            mx1 = fmaxf(mx1, fmaxf(sv[nt][2], sv[nt][3]));
        }
        mx0 = fmaxf(mx0, __shfl_xor_sync(0xffffffffu, mx0, 1));
        mx0 = fmaxf(mx0, __shfl_xor_sync(0xffffffffu, mx0, 2));
        mx1 = fmaxf(mx1, __shfl_xor_sync(0xffffffffu, mx1, 1));
        mx1 = fmaxf(mx1, __shfl_xor_sync(0xffffffffu, mx1, 2));

        float mn0 = fmaxf(m0v, mx0), mn1 = fmaxf(m1v, mx1);
        float c0 = __expf(m0v - mn0), c1 = __expf(m1v - mn1);
        m0v = mn0; m1v = mn1;

        float rs0 = 0.f, rs1 = 0.f;
        #pragma unroll
        for (int nt = 0; nt < 8; ++nt) {
            sv[nt][0] = __expf(sv[nt][0] - mn0);
            sv[nt][1] = __expf(sv[nt][1] - mn0);
            sv[nt][2] = __expf(sv[nt][2] - mn1);
            sv[nt][3] = __expf(sv[nt][3] - mn1);
            rs0 += sv[nt][0] + sv[nt][1];
            rs1 += sv[nt][2] + sv[nt][3];
        }
        rs0 += __shfl_xor_sync(0xffffffffu, rs0, 1);
        rs0 += __shfl_xor_sync(0xffffffffu, rs0, 2);
        rs1 += __shfl_xor_sync(0xffffffffu, rs1, 1);
        rs1 += __shfl_xor_sync(0xffffffffu, rs1, 2);
        l0 = l0 * c0 + rs0;
        l1 = l1 * c1 + rs1;

        #pragma unroll
        for (int nt = 0; nt < 8; ++nt) {
            o[nt][0] *= c0; o[nt][1] *= c0;
            o[nt][2] *= c1; o[nt][3] *= c1;
        }

        // ---- O += P @ V ---- (P split in regs; V via ldmatrix.trans)
        #pragma unroll
        for (int kt = 0; kt < 4; ++kt) {
            uint32_t ph[4], pl[4];
            splitpair(sv[2*kt][0],   sv[2*kt][1],   ph[0], pl[0]);
            splitpair(sv[2*kt][2],   sv[2*kt][3],   ph[1], pl[1]);
            splitpair(sv[2*kt+1][0], sv[2*kt+1][1], ph[2], pl[2]);
            splitpair(sv[2*kt+1][2], sv[2*kt+1][3], ph[3], pl[3]);
            #pragma unroll
            for (int np = 0; np < 4; ++np) {
                uint32_t va = vbh + (kt * 16 + v_ro) * APB + np * 32 + v_db;
                uint32_t vh4[4], vl4[4];
                ldm_x4t(vh4, va);
                ldm_x4t(vl4, va + KPLB);
                #pragma unroll
                for (int hf = 0; hf < 2; ++hf) {
                    int nt = np * 2 + hf;
                    uint32_t v2h[2] = {vh4[hf*2], vh4[hf*2+1]};
                    uint32_t v2l[2] = {vl4[hf*2], vl4[hf*2+1]};
                    MMA_BF16(o[nt], ph, v2h);
                    MMA_BF16(o[nt], ph, v2l);
                    MMA_BF16(o[nt], pl, v2h);
                }
            }
        }
        s ^= 1;
    }

    // ---- Epilogue: write o hi/lo planes ----
    float inv0 = 1.f / l0, inv1 = 1.f / l1;
    size_t r0w = wbase + (size_t)(qb * QT + wm + quad) * (DIM / 2);
    size_t r1w = r0w + 8 * (DIM / 2);
    #pragma unroll
    for (int nt = 0; nt < 8; ++nt) {
        int cw = nt * 4 + tq;
        uint32_t hw, lw;
        splitpair(o[nt][0] * inv0, o[nt][1] * inv0, hw, lw);
        Oh[r0w + cw] = hw; Ol[r0w + cw] = lw;
        splitpair(o[nt][2] * inv1, o[nt][3] * inv1, hw, lw);
        Oh[r1w + cw] = hw; Ol[r1w + cw] = lw;
    }
}

// ---------------------------------------------------------------------------
extern "C" void kernel_launch(void* const* d_in, const int* in_sizes, int n_in,
                              void* d_out, int out_size)
{
    const float* x  = (const float*)d_in[0];
    const float* Wq = (const float*)d_in[1];
    const float* bq = (const float*)d_in[2];
    const float* Wk = (const float*)d_in[3];
    const float* bk = (const float*)d_in[4];
    const float* Wv = (const float*)d_in[5];
    const float* bv = (const float*)d_in[6];
    const float* Wo = (const float*)d_in[7];
    const float* bo = (const float*)d_in[8];

    __nv_bfloat16 *xh, *xl, *wh, *wl, *qh, *ql, *kh, *kl, *vh, *vl, *oh, *ol;
    cudaGetSymbolAddress((void**)&xh, g_xh); cudaGetSymbolAddress((void**)&xl, g_xl);
    cudaGetSymbolAddress((void**)&wh, g_wh); cudaGetSymbolAddress((void**)&wl, g_wl);
    cudaGetSymbolAddress((void**)&qh, g_qh); cudaGetSymbolAddress((void**)&ql, g_ql);
    cudaGetSymbolAddress((void**)&kh, g_kh); cudaGetSymbolAddress((void**)&kl, g_kl);
    cudaGetSymbolAddress((void**)&vh, g_vh); cudaGetSymbolAddress((void**)&vl, g_vl);
    cudaGetSymbolAddress((void**)&oh, g_oh); cudaGetSymbolAddress((void**)&ol, g_ol);

    // prep: fp32 -> bf16 hi/lo planes
    int n4x = MTOT * DIM / 4;
    split_planes_kernel<<<(n4x + 255) / 256, 256>>>(x, xh, xl, n4x);
    int n4w = DIM * DIM / 4;
    split_planes_kernel<<<(n4w + 255) / 256, 256>>>(Wq, wh,               wl,               n4w);
    split_planes_kernel<<<(n4w + 255) / 256, 256>>>(Wk, wh +   DIM*DIM,   wl +   DIM*DIM,   n4w);
    split_planes_kernel<<<(n4w + 255) / 256, 256>>>(Wv, wh + 2*DIM*DIM,   wl + 2*DIM*DIM,   n4w);
    split_planes_kernel<<<(n4w + 255) / 256, 256>>>(Wo, wh + 3*DIM*DIM,   wl + 3*DIM*DIM,   n4w);

    int gsmem = 2 * GSTAGEB;   // 81920
    cudaFuncSetAttribute(gemm_planes_kernel<0>, cudaFuncAttributeMaxDynamicSharedMemorySize, gsmem);
    cudaFuncSetAttribute(gemm_planes_kernel<1>, cudaFuncAttributeMaxDynamicSharedMemorySize, gsmem);

    // fused QKV projections (grid.z selects q/k/v)
    dim3 qkvgrid(DIM / GBN, MTOT / GBM, 3);
    gemm_planes_kernel<0><<<qkvgrid, 256, gsmem>>>(
        xh, xl, wh, wl, bq, bk, bv,
        (uint32_t*)qh, (uint32_t*)ql, (uint32_t*)kh, (uint32_t*)kl,
        (uint32_t*)vh, (uint32_t*)vl, nullptr);

    // attention
    int asmem = 2 * ASTAGEB;   // 73728
    cudaFuncSetAttribute(attn_mma_kernel, cudaFuncAttributeMaxDynamicSharedMemorySize, asmem);
    attn_mma_kernel<<<dim3(SEQ / QT, NH, BATCH), 256, asmem>>>(
        qh, ql, kh, kl, vh, vl, (uint32_t*)oh, (uint32_t*)ol);

    // output projection (fp32 out)
    dim3 ogrid(DIM / GBN, MTOT / GBM, 1);
    gemm_planes_kernel<1><<<ogrid, 256, gsmem>>>(
        oh, ol, wh + 3*DIM*DIM, wl + 3*DIM*DIM, bo, nullptr, nullptr,
        nullptr, nullptr, nullptr, nullptr, nullptr, nullptr, (float*)d_out);
}